// round 5
// baseline (speedup 1.0000x reference)
#include <cuda_runtime.h>
#include <math.h>

// Problem constants (fixed by reference)
#define BB     32          // batch
#define TT     64          // timesteps
#define DD     512         // d_emb / LSTM units
#define DCNT   128         // d_content
#define DSTY   16          // d_style
#define H4     2048        // 4 * units
#define VV     32000       // vocab
#define VCHUNK 256
#define NBLK   125         // VV / VCHUNK
#define WSTRIDE 36         // padded smem row stride for exp-weights (16B aligned, low conflicts)
#define NCHUNK 9           // K-split chunks for LSTM GEMM
#define SMEM_BYTES ((DD*BB + VCHUNK*WSTRIDE + 256) * 4)

// Persistent device state / scratch (no allocations allowed)
__device__ __align__(16) float g_hbuf[2][BB*DD];
__device__ __align__(16) float g_cbuf[2][BB*DD];
__device__ __align__(16) float g_hT[DD*BB];           // h in [k][b] layout
__device__ __align__(16) float g_emb[BB*DD];          // current soft embedding
__device__ __align__(16) float g_zpart[NCHUNK][BB][H4];
__device__ __align__(16) float g_acc[NBLK*BB*DD];     // partial weighted-E accumulators
__device__ __align__(16) float g_psum[NBLK*BB];       // partial exp sums

// ---------- packed f32x2 helpers (B300 PTX) ----------
static __device__ __forceinline__ unsigned long long ffma2(unsigned long long a,
                                                           unsigned long long b,
                                                           unsigned long long c) {
    unsigned long long d;
    asm("fma.rn.f32x2 %0, %1, %2, %3;" : "=l"(d) : "l"(a), "l"(b), "l"(c));
    return d;
}
static __device__ __forceinline__ unsigned long long pack2(float x, float y) {
    unsigned long long r;
    asm("mov.b64 %0, {%1, %2};" : "=l"(r) : "f"(x), "f"(y));
    return r;
}
static __device__ __forceinline__ float2 unpack2(unsigned long long v) {
    float2 r;
    asm("mov.b64 {%0, %1}, %2;" : "=f"(r.x), "=f"(r.y) : "l"(v));
    return r;
}
static __device__ __forceinline__ float sigf(float x) { return 1.0f / (1.0f + expf(-x)); }

// ---------- t = 0: SOS embedding, zero state ----------
__global__ void k_init(const float* __restrict__ E, float* __restrict__ out) {
    int b = blockIdx.x, d = threadIdx.x;       // grid 32, block 512
    float e = E[d];                            // E[SOS=0][d]
    g_emb[b*DD + d] = e;
    out[(size_t)(b*TT)*DD + d] = e;
    g_hbuf[0][b*DD + d] = 0.f;
    g_cbuf[0][b*DD + d] = 0.f;
}

// ---------- LSTM gate GEMM, K-split partials ----------
static __device__ __forceinline__ void fma4(float (&acc)[4][4], float x, const float* wb) {
    #pragma unroll
    for (int g = 0; g < 4; g++) {
        float4 w = *(const float4*)(wb + g*DD);
        acc[g][0] += x * w.x; acc[g][1] += x * w.y;
        acc[g][2] += x * w.z; acc[g][3] += x * w.w;
    }
}

__global__ __launch_bounds__(256) void k_lstm_mm(
    const float* __restrict__ content, const float* __restrict__ style,
    const float* __restrict__ Wk, const float* __restrict__ Wr, int cur)
{
    int tid = threadIdx.x;
    int b  = tid >> 3;                 // 0..31
    int jl = tid & 7;                  // 0..7
    int j0 = blockIdx.x * 32 + jl * 4; // 4 consecutive output units
    int ch = blockIdx.y;               // K chunk 0..8

    float acc[4][4];
    #pragma unroll
    for (int g = 0; g < 4; g++) {
        acc[g][0] = 0.f; acc[g][1] = 0.f; acc[g][2] = 0.f; acc[g][3] = 0.f;
    }

    if (ch < 4) {                                   // emb part of x @ Wk
        const float* Wb = Wk + (size_t)(ch*128)*H4 + j0;
        const float* xp = g_emb + b*DD + ch*128;
        #pragma unroll 4
        for (int k = 0; k < 128; k++) fma4(acc, xp[k], Wb + (size_t)k*H4);
    } else if (ch == 4) {                           // content + style
        const float* Wb = Wk + (size_t)512*H4 + j0;
        const float* xp = content + b*DCNT;
        #pragma unroll 4
        for (int k = 0; k < DCNT; k++) fma4(acc, xp[k], Wb + (size_t)k*H4);
        Wb = Wk + (size_t)640*H4 + j0;
        xp = style + b*DSTY;
        #pragma unroll
        for (int k = 0; k < DSTY; k++) fma4(acc, xp[k], Wb + (size_t)k*H4);
    } else {                                        // h @ Wr
        int c2 = ch - 5;
        const float* Wb = Wr + (size_t)(c2*128)*H4 + j0;
        const float* xp = g_hbuf[cur ^ 1] + b*DD + c2*128;
        #pragma unroll 4
        for (int k = 0; k < 128; k++) fma4(acc, xp[k], Wb + (size_t)k*H4);
    }

    float* zp = &g_zpart[ch][b][0];
    #pragma unroll
    for (int g = 0; g < 4; g++)
        *(float4*)(zp + g*DD + j0) = make_float4(acc[g][0], acc[g][1], acc[g][2], acc[g][3]);
}

// ---------- LSTM epilogue: reduce chunks, gates, state update ----------
__global__ __launch_bounds__(512) void k_lstm_fin(const float* __restrict__ bias, int cur) {
    int b = blockIdx.x, j = threadIdx.x;   // grid 32, block 512
    float z0 = bias[j], z1 = bias[DD + j], z2 = bias[2*DD + j], z3 = bias[3*DD + j];
    #pragma unroll
    for (int ch = 0; ch < NCHUNK; ch++) {
        const float* zp = &g_zpart[ch][b][0];
        z0 += zp[j]; z1 += zp[DD + j]; z2 += zp[2*DD + j]; z3 += zp[3*DD + j];
    }
    float iv = sigf(z0), fv = sigf(z1), gv = tanhf(z2), ov = sigf(z3);
    float c = fv * g_cbuf[cur ^ 1][b*DD + j] + iv * gv;
    float h = ov * tanhf(c);
    g_cbuf[cur][b*DD + j] = c;
    g_hbuf[cur][b*DD + j] = h;
    g_hT[j*BB + b] = h;                    // k-major for the vocab kernel
}

// ---------- fused logits -> exp -> partial (exp @ E) over a vocab chunk ----------
__global__ __launch_bounds__(256) void k_vocab(
    const float* __restrict__ Ws, const float* __restrict__ bs,
    const float* __restrict__ E)
{
    extern __shared__ float sm[];
    float* Hs   = sm;                       // [512][32] h, k-major
    float* Wexp = sm + DD*BB;               // [VCHUNK][WSTRIDE] exp weights, b contiguous
    float* red  = Wexp + VCHUNK*WSTRIDE;    // [8][32] partial-sum scratch
    int tid = threadIdx.x;

    // stage H (coalesced float4 copy)
    {
        const float4* src = (const float4*)g_hT;
        float4* dst = (float4*)Hs;
        for (int i = tid; i < DD*BB/4; i += 256) dst[i] = src[i];
    }
    __syncthreads();

    int v0 = blockIdx.x * VCHUNK;
    int v  = v0 + tid;                      // blockDim == VCHUNK

    // Phase 1: logits for 32 batch rows at vocab index v (packed batch pairs)
    {
        unsigned long long acc[16];
        #pragma unroll
        for (int i = 0; i < 16; i++) acc[i] = 0ULL;
        const float* wcol = Ws + v;
        #pragma unroll 4
        for (int k = 0; k < DD; k++) {
            float ws = wcol[(size_t)k * VV];                 // coalesced 128B/warp
            unsigned long long ws2 = pack2(ws, ws);
            const ulonglong2* hp = (const ulonglong2*)(Hs + k*BB);  // packed {h_b,h_b+1}
            #pragma unroll
            for (int i = 0; i < 8; i++) {
                ulonglong2 q = hp[i];
                acc[2*i]   = ffma2(q.x, ws2, acc[2*i]);
                acc[2*i+1] = ffma2(q.y, ws2, acc[2*i+1]);
            }
        }
        float bv = bs[v];
        float* wr = Wexp + tid*WSTRIDE;
        #pragma unroll
        for (int i = 0; i < 16; i++) {
            float2 l = unpack2(acc[i]);
            wr[2*i]   = expf(l.x + bv);     // |logit| small by construction: no max shift needed
            wr[2*i+1] = expf(l.y + bv);
        }
    }
    __syncthreads();

    // Phase 1.5: deterministic per-batch partial sums of exp weights
    {
        int b2 = tid & 31, slice = tid >> 5;
        float s = 0.f;
        for (int vv = slice; vv < VCHUNK; vv += 8) s += Wexp[vv*WSTRIDE + b2];
        red[slice*32 + b2] = s;
    }
    __syncthreads();
    if (tid < 32) {
        float s = 0.f;
        #pragma unroll
        for (int i = 0; i < 8; i++) s += red[i*32 + tid];
        g_psum[blockIdx.x*BB + tid] = s;
    }

    // Phase 2: partial weighted embedding  acc[b][d] += w[v][b] * E[v][d]
    {
        unsigned long long ax[16], ay[16];
        #pragma unroll
        for (int i = 0; i < 16; i++) { ax[i] = 0ULL; ay[i] = 0ULL; }
        const float2* E2 = (const float2*)E;    // thread owns d0=2*tid, d1=2*tid+1
        #pragma unroll 2
        for (int vv = 0; vv < VCHUNK; vv++) {
            float2 e = E2[(size_t)(v0 + vv)*(DD/2) + tid];
            unsigned long long ex2 = pack2(e.x, e.x);
            unsigned long long ey2 = pack2(e.y, e.y);
            const ulonglong2* wp = (const ulonglong2*)(Wexp + vv*WSTRIDE);
            #pragma unroll
            for (int i = 0; i < 8; i++) {
                ulonglong2 q = wp[i];                // {w_b, w_b+1} packed
                ax[2*i]   = ffma2(q.x, ex2, ax[2*i]);
                ay[2*i]   = ffma2(q.x, ey2, ay[2*i]);
                ax[2*i+1] = ffma2(q.y, ex2, ax[2*i+1]);
                ay[2*i+1] = ffma2(q.y, ey2, ay[2*i+1]);
            }
        }
        float2* gout = (float2*)g_acc;
        int base = blockIdx.x * BB;
        #pragma unroll
        for (int i = 0; i < 16; i++) {
            float2 x2 = unpack2(ax[i]);   // {d0 | b=2i , d0 | b=2i+1}
            float2 y2 = unpack2(ay[i]);   // {d1 | b=2i , d1 | b=2i+1}
            gout[(size_t)(base + 2*i    )*(DD/2) + tid] = make_float2(x2.x, y2.x);
            gout[(size_t)(base + 2*i + 1)*(DD/2) + tid] = make_float2(x2.y, y2.y);
        }
    }
}

// ---------- final reduce: normalize soft embedding, write output ----------
__global__ __launch_bounds__(256) void k_reduce(float* __restrict__ out, int t) {
    int b = blockIdx.x, tid = threadIdx.x;  // grid 32, block 256 (2 dims each)
    float tot = 0.f;
    for (int blk = 0; blk < NBLK; blk++) tot += g_psum[blk*BB + b];
    float inv = 1.0f / tot;
    float2 a = make_float2(0.f, 0.f);
    const float2* gin = (const float2*)g_acc;
    for (int blk = 0; blk < NBLK; blk++) {
        float2 p = gin[(size_t)(blk*BB + b)*(DD/2) + tid];
        a.x += p.x; a.y += p.y;
    }
    a.x *= inv; a.y *= inv;
    ((float2*)g_emb)[b*(DD/2) + tid] = a;
    ((float2*)out)[((size_t)b*TT + t)*(DD/2) + tid] = a;
}

extern "C" void kernel_launch(void* const* d_in, const int* in_sizes, int n_in,
                              void* d_out, int out_size) {
    const float* content = (const float*)d_in[0];
    const float* style   = (const float*)d_in[1];
    const float* E       = (const float*)d_in[2];
    const float* Wk      = (const float*)d_in[3];
    const float* Wr      = (const float*)d_in[4];
    const float* bias    = (const float*)d_in[5];
    const float* Ws      = (const float*)d_in[6];
    const float* bs      = (const float*)d_in[7];
    float* out = (float*)d_out;

    cudaFuncSetAttribute((const void*)k_vocab,
                         cudaFuncAttributeMaxDynamicSharedMemorySize, SMEM_BYTES);

    k_init<<<BB, DD>>>(E, out);
    for (int t = 1; t < TT; t++) {
        int cur = t & 1;
        k_lstm_mm<<<dim3(16, NCHUNK), 256>>>(content, style, Wk, Wr, cur);
        k_lstm_fin<<<BB, DD>>>(bias, cur);
        k_vocab<<<NBLK, VCHUNK, SMEM_BYTES>>>(Ws, bs, E);
        k_reduce<<<BB, DD/2>>>(out, t);
    }
}

// round 7
// speedup vs baseline: 2.0817x; 2.0817x over previous
#include <cuda_runtime.h>
#include <math.h>

// Problem constants (fixed by reference)
#define BB     32          // batch
#define TT     64          // timesteps
#define DD     512         // d_emb / LSTM units
#define H4     2048        // 4 * units
#define VV     32000       // vocab
#define NCH    19          // LSTM K chunks (8 emb + 2 content + 1 style + 8 h)
#define NPB    125         // vocab blocks of 256 (psum partials)
#define ECH    250         // emb partial chunks (128 vocab each)

// Persistent device state / scratch (no allocations allowed)
__device__ __align__(16) float g_hbuf[2][BB*DD];
__device__ __align__(16) float g_cbuf[2][BB*DD];
__device__ __align__(16) float g_hT[DD*BB];          // h in [k][b] layout
__device__ __align__(16) float g_emb[BB*DD];         // current soft embedding
__device__ __align__(16) float g_zpart[NCH][BB][H4]; // LSTM gate partials
__device__ __align__(16) float g_zl[4][VV*BB];       // logit K-quarter partials
__device__ __align__(16) float g_P[VV*BB];           // exp(logits), [v][b]
__device__ __align__(16) float g_acc[(size_t)ECH*BB*DD]; // weighted-E partials
__device__ __align__(16) float g_psum[NPB*BB];       // exp partial sums

// ---------- packed f32x2 helpers ----------
static __device__ __forceinline__ unsigned long long ffma2(unsigned long long a,
                                                           unsigned long long b,
                                                           unsigned long long c) {
    unsigned long long d;
    asm("fma.rn.f32x2 %0, %1, %2, %3;" : "=l"(d) : "l"(a), "l"(b), "l"(c));
    return d;
}
static __device__ __forceinline__ unsigned long long pack2(float x, float y) {
    unsigned long long r;
    asm("mov.b64 %0, {%1, %2};" : "=l"(r) : "f"(x), "f"(y));
    return r;
}
static __device__ __forceinline__ float2 unpack2(unsigned long long v) {
    float2 r;
    asm("mov.b64 {%0, %1}, %2;" : "=f"(r.x), "=f"(r.y) : "l"(v));
    return r;
}
static __device__ __forceinline__ float sigf(float x) { return 1.0f / (1.0f + expf(-x)); }

// ---------- t = 0: SOS embedding, zero state ----------
__global__ void k_init(const float* __restrict__ E, float* __restrict__ out) {
    int b = blockIdx.x, d = threadIdx.x;       // grid 32, block 512
    float e = E[d];                            // E[SOS=0][d]
    g_emb[b*DD + d] = e;
    out[(size_t)(b*TT)*DD + d] = e;
    g_hbuf[0][b*DD + d] = 0.f;
    g_cbuf[0][b*DD + d] = 0.f;
}

// ---------- LSTM gate GEMM, K-split partials (chunks of 64) ----------
static __device__ __forceinline__ void fma4p(unsigned long long (&acc)[4][2],
                                             float x, const float* wb) {
    unsigned long long x2 = pack2(x, x);
    #pragma unroll
    for (int g = 0; g < 4; g++) {
        float4 w = *(const float4*)(wb + g*DD);
        acc[g][0] = ffma2(pack2(w.x, w.y), x2, acc[g][0]);
        acc[g][1] = ffma2(pack2(w.z, w.w), x2, acc[g][1]);
    }
}

__global__ __launch_bounds__(256) void k_lstm_mm(
    const float* __restrict__ content, const float* __restrict__ style,
    const float* __restrict__ Wk, const float* __restrict__ Wr, int cur)
{
    int tid = threadIdx.x;
    int b  = tid >> 3;                 // 0..31
    int jl = tid & 7;                  // 0..7
    int j0 = blockIdx.x * 32 + jl * 4; // 4 consecutive output units per gate
    int ch = blockIdx.y;               // K chunk 0..18

    unsigned long long acc[4][2];
    #pragma unroll
    for (int g = 0; g < 4; g++) { acc[g][0] = 0ULL; acc[g][1] = 0ULL; }

    const float* Wb; const float* xp; int n;
    if (ch < 8)       { Wb = Wk + (size_t)(ch*64)*H4 + j0;           xp = g_emb + b*DD + ch*64;              n = 64; }
    else if (ch < 10) { Wb = Wk + (size_t)(512+(ch-8)*64)*H4 + j0;   xp = content + b*128 + (ch-8)*64;       n = 64; }
    else if (ch == 10){ Wb = Wk + (size_t)640*H4 + j0;               xp = style + b*16;                      n = 16; }
    else              { Wb = Wr + (size_t)((ch-11)*64)*H4 + j0;      xp = g_hbuf[cur^1] + b*DD + (ch-11)*64; n = 64; }

    #pragma unroll 4
    for (int k = 0; k < n; k++) fma4p(acc, xp[k], Wb + (size_t)k*H4);

    float* zp = &g_zpart[ch][b][0];
    #pragma unroll
    for (int g = 0; g < 4; g++) {
        float2 a = unpack2(acc[g][0]);
        float2 c = unpack2(acc[g][1]);
        *(float4*)(zp + g*DD + j0) = make_float4(a.x, a.y, c.x, c.y);
    }
}

// ---------- LSTM epilogue: reduce chunks, gates, state update ----------
__global__ __launch_bounds__(512) void k_lstm_fin(const float* __restrict__ bias, int cur) {
    int b = blockIdx.x, j = threadIdx.x;   // grid 32, block 512
    float z0 = bias[j], z1 = bias[DD + j], z2 = bias[2*DD + j], z3 = bias[3*DD + j];
    #pragma unroll
    for (int ch = 0; ch < NCH; ch++) {
        const float* zp = &g_zpart[ch][b][0];
        z0 += zp[j]; z1 += zp[DD + j]; z2 += zp[2*DD + j]; z3 += zp[3*DD + j];
    }
    float iv = sigf(z0), fv = sigf(z1), gv = tanhf(z2), ov = sigf(z3);
    float c = fv * g_cbuf[cur ^ 1][b*DD + j] + iv * gv;
    float h = ov * tanhf(c);
    g_cbuf[cur][b*DD + j] = c;
    g_hbuf[cur][b*DD + j] = h;
    g_hT[j*BB + b] = h;                    // k-major for the logits kernel
}

// ---------- partial logits: one K-quarter per block, no combine ----------
// grid (125 vchunks, 4 kq), block 256: thread = one vocab column, K=128.
__global__ __launch_bounds__(256) void k_zl(const float* __restrict__ Ws)
{
    __shared__ __align__(16) float Hs[128*BB];   // 16KB: one K-quarter of h
    int tid = threadIdx.x;
    int kq = blockIdx.y;
    int v = blockIdx.x * 256 + tid;

    {   // stage H quarter (rows kq*128 .. kq*128+127)
        const float4* src = (const float4*)(g_hT + kq*128*BB);
        float4* dst = (float4*)Hs;
        #pragma unroll
        for (int i = 0; i < 4; i++) dst[tid + 256*i] = src[tid + 256*i];
    }
    __syncthreads();

    unsigned long long acc[16];
    #pragma unroll
    for (int i = 0; i < 16; i++) acc[i] = 0ULL;

    const float* wcol = Ws + (size_t)(kq*128)*VV + v;
    #pragma unroll 4
    for (int k = 0; k < 128; k++) {
        float ws = wcol[(size_t)k * VV];                 // coalesced 128B/warp
        unsigned long long ws2 = pack2(ws, ws);
        const ulonglong2* hr = (const ulonglong2*)(Hs + k*BB);  // broadcast LDS.128
        #pragma unroll
        for (int i = 0; i < 8; i++) {
            ulonglong2 q = hr[i];
            acc[2*i]   = ffma2(q.x, ws2, acc[2*i]);      // batches (4i,4i+1)
            acc[2*i+1] = ffma2(q.y, ws2, acc[2*i+1]);    // batches (4i+2,4i+3)
        }
    }

    float4* o = (float4*)(g_zl[kq] + (size_t)v*BB);      // acc[j] = batches (2j,2j+1)
    #pragma unroll
    for (int i = 0; i < 8; i++) {
        float2 a = unpack2(acc[2*i]);
        float2 c = unpack2(acc[2*i+1]);
        o[i] = make_float4(a.x, a.y, c.x, c.y);
    }
}

// ---------- sum partials + exp -> g_P, per-block psum ----------
// grid 125, block 256: thread = one vocab column.
__global__ __launch_bounds__(256) void k_exps(const float* __restrict__ bs)
{
    __shared__ float sm[256*33 + 256];     // stash rows + red scratch (34.8KB)
    int tid = threadIdx.x;
    int v = blockIdx.x * 256 + tid;

    float w[32];
    {
        const float4* p0 = (const float4*)(g_zl[0] + (size_t)v*BB);
        const float4* p1 = (const float4*)(g_zl[1] + (size_t)v*BB);
        const float4* p2 = (const float4*)(g_zl[2] + (size_t)v*BB);
        const float4* p3 = (const float4*)(g_zl[3] + (size_t)v*BB);
        #pragma unroll
        for (int i = 0; i < 8; i++) {
            float4 a = p0[i], b4 = p1[i], c4 = p2[i], d4 = p3[i];
            w[4*i]   = a.x + b4.x + c4.x + d4.x;
            w[4*i+1] = a.y + b4.y + c4.y + d4.y;
            w[4*i+2] = a.z + b4.z + c4.z + d4.z;
            w[4*i+3] = a.w + b4.w + c4.w + d4.w;
        }
    }
    float bv = bs[v];
    #pragma unroll
    for (int b = 0; b < 32; b++) w[b] = expf(w[b] + bv);  // |logit| small: safe

    float4* pout = (float4*)(g_P + (size_t)v*BB);
    #pragma unroll
    for (int i = 0; i < 8; i++)
        pout[i] = make_float4(w[4*i], w[4*i+1], w[4*i+2], w[4*i+3]);

    float* srow = sm + tid*33;
    #pragma unroll
    for (int b = 0; b < 32; b++) srow[b] = w[b];
    __syncthreads();

    {   // two-stage per-batch sum over 256 vocab (deterministic)
        int b2 = tid & 31, sl = tid >> 5;
        float s = 0.f;
        #pragma unroll 4
        for (int u = sl; u < 256; u += 8) s += sm[u*33 + b2];
        sm[256*33 + sl*32 + b2] = s;
    }
    __syncthreads();
    if (tid < 32) {
        float s = 0.f;
        #pragma unroll
        for (int i = 0; i < 8; i++) s += sm[256*33 + i*32 + tid];
        g_psum[blockIdx.x*BB + tid] = s;
    }
}

// ---------- partial (exp @ E): grid (125 vchunks, 4 dq), block 256 ----------
// tid = dl(0..127) + 128*vh(0..1). Each thread: 1 d column, 32 batches, 128 vocab.
__global__ __launch_bounds__(256, 4) void k_emb(const float* __restrict__ E)
{
    extern __shared__ float smP[];          // 8192 floats = 32KB: P[256][32]
    int tid = threadIdx.x;
    int dl = tid & 127, vh = tid >> 7;
    int v0 = blockIdx.x * 256;
    int d0 = blockIdx.y * 128;

    {
        const float4* src = (const float4*)(g_P + (size_t)v0*BB);
        float4* dst = (float4*)smP;
        #pragma unroll
        for (int i = 0; i < 8; i++) dst[tid + 256*i] = src[tid + 256*i];
    }
    __syncthreads();

    unsigned long long acc[16];
    #pragma unroll
    for (int i = 0; i < 16; i++) acc[i] = 0ULL;

    const float* ecol = E + (size_t)(v0 + vh*128)*DD + d0 + dl;
    const ulonglong2* wp0 = (const ulonglong2*)(smP + vh*128*BB);
    #pragma unroll 2
    for (int vv = 0; vv < 128; vv++) {
        float e = ecol[(size_t)vv * DD];                   // coalesced 128B/warp
        unsigned long long e2 = pack2(e, e);
        const ulonglong2* wr = wp0 + vv*8;                 // broadcast LDS.128
        #pragma unroll
        for (int i = 0; i < 8; i++) {
            ulonglong2 q = wr[i];
            acc[2*i]   = ffma2(q.x, e2, acc[2*i]);
            acc[2*i+1] = ffma2(q.y, e2, acc[2*i+1]);
        }
    }

    int pc = blockIdx.x*2 + vh;            // 0..249 partial chunk
    float* ob = g_acc + ((size_t)pc*BB)*DD + d0 + dl;
    #pragma unroll
    for (int i = 0; i < 16; i++) {
        float2 t = unpack2(acc[i]);
        ob[(size_t)(2*i)  *DD] = t.x;
        ob[(size_t)(2*i+1)*DD] = t.y;
    }
}

// ---------- final reduce: normalize soft embedding, write output ----------
// grid (32 b, 8 dgroups), block 256 (8 slices x 32 float2 lanes)
__global__ __launch_bounds__(256) void k_reduce(float* __restrict__ out, int t) {
    __shared__ float2 red[8][32];
    __shared__ float s_inv;
    int b = blockIdx.x, dg = blockIdx.y;
    int tid = threadIdx.x;
    int s = tid >> 5, d2l = tid & 31;

    float2 a = make_float2(0.f, 0.f);
    const float2* gin = (const float2*)g_acc;
    for (int c = s; c < ECH; c += 8) {
        float2 p = gin[((size_t)c*BB + b)*(DD/2) + dg*32 + d2l];
        a.x += p.x; a.y += p.y;
    }
    red[s][d2l] = a;

    if (tid < 32) {                        // deterministic softmax denominator
        float ts = 0.f;
        for (int c = tid; c < NPB; c += 32) ts += g_psum[c*BB + b];
        #pragma unroll
        for (int o = 16; o > 0; o >>= 1) ts += __shfl_xor_sync(0xffffffffu, ts, o);
        if (tid == 0) s_inv = 1.0f / ts;
    }
    __syncthreads();

    if (s == 0) {
        #pragma unroll
        for (int i = 1; i < 8; i++) { a.x += red[i][d2l].x; a.y += red[i][d2l].y; }
        float inv = s_inv;
        a.x *= inv; a.y *= inv;
        int d2 = dg*32 + d2l;
        ((float2*)g_emb)[b*(DD/2) + d2] = a;
        ((float2*)out)[((size_t)b*TT + t)*(DD/2) + d2] = a;
    }
}

extern "C" void kernel_launch(void* const* d_in, const int* in_sizes, int n_in,
                              void* d_out, int out_size) {
    const float* content = (const float*)d_in[0];
    const float* style   = (const float*)d_in[1];
    const float* E       = (const float*)d_in[2];
    const float* Wk      = (const float*)d_in[3];
    const float* Wr      = (const float*)d_in[4];
    const float* bias    = (const float*)d_in[5];
    const float* Ws      = (const float*)d_in[6];
    const float* bs      = (const float*)d_in[7];
    float* out = (float*)d_out;

    cudaFuncSetAttribute((const void*)k_emb,
                         cudaFuncAttributeMaxDynamicSharedMemorySize, 8192*4);

    k_init<<<BB, DD>>>(E, out);
    for (int t = 1; t < TT; t++) {
        int cur = t & 1;
        k_lstm_mm<<<dim3(16, NCH), 256>>>(content, style, Wk, Wr, cur);
        k_lstm_fin<<<BB, DD>>>(bias, cur);
        k_zl<<<dim3(NPB, 4), 256>>>(Ws);
        k_exps<<<NPB, 256>>>(bs);
        k_emb<<<dim3(NPB, 4), 256, 8192*4>>>(E);
        k_reduce<<<dim3(BB, 8), 256>>>(out, t);
    }
}

// round 8
// speedup vs baseline: 2.4143x; 1.1598x over previous
#include <cuda_runtime.h>
#include <math.h>

// Problem constants (fixed by reference)
#define BB     32          // batch
#define TT     64          // timesteps
#define DD     512         // d_emb / LSTM units
#define H4     2048        // 4 * units
#define VV     32000       // vocab
#define NCH    19          // LSTM K chunks (8 emb + 2 content + 1 style + 8 h)
#define NVB    250         // vocab blocks of 128 (psum / emb partial chunks)

// Persistent device state / scratch (no allocations allowed)
__device__ __align__(16) float g_hbuf[2][BB*DD];
__device__ __align__(16) float g_cbuf[2][BB*DD];
__device__ __align__(16) float g_hT[DD*BB];          // h in [k][b] layout
__device__ __align__(16) float g_emb[BB*DD];         // current soft embedding
__device__ __align__(16) float g_zpart[NCH][BB][H4]; // LSTM gate partials
__device__ __align__(16) float g_zl[4][VV*BB];       // logit K-quarter partials
__device__ __align__(16) float g_P[VV*BB];           // exp(logits), [v][b]
__device__ __align__(16) float g_acc[(size_t)NVB*BB*DD]; // weighted-E partials
__device__ __align__(16) float g_psum[NVB*BB];       // exp partial sums

// ---------- packed f32x2 helpers ----------
static __device__ __forceinline__ unsigned long long ffma2(unsigned long long a,
                                                           unsigned long long b,
                                                           unsigned long long c) {
    unsigned long long d;
    asm("fma.rn.f32x2 %0, %1, %2, %3;" : "=l"(d) : "l"(a), "l"(b), "l"(c));
    return d;
}
static __device__ __forceinline__ unsigned long long pack2(float x, float y) {
    unsigned long long r;
    asm("mov.b64 %0, {%1, %2};" : "=l"(r) : "f"(x), "f"(y));
    return r;
}
static __device__ __forceinline__ float2 unpack2(unsigned long long v) {
    float2 r;
    asm("mov.b64 {%0, %1}, %2;" : "=f"(r.x), "=f"(r.y) : "l"(v));
    return r;
}
static __device__ __forceinline__ float sigf(float x) { return 1.0f / (1.0f + expf(-x)); }

// ---------- t = 0: SOS embedding, zero state ----------
__global__ void k_init(const float* __restrict__ E, float* __restrict__ out) {
    int b = blockIdx.x, d = threadIdx.x;       // grid 32, block 512
    float e = E[d];                            // E[SOS=0][d]
    g_emb[b*DD + d] = e;
    out[(size_t)(b*TT)*DD + d] = e;
    g_hbuf[0][b*DD + d] = 0.f;
    g_cbuf[0][b*DD + d] = 0.f;
}

// ---------- LSTM gate GEMM, K-split partials (chunks of 64) ----------
static __device__ __forceinline__ void fma4p(unsigned long long (&acc)[4][2],
                                             float x, const float* wb) {
    unsigned long long x2 = pack2(x, x);
    #pragma unroll
    for (int g = 0; g < 4; g++) {
        float4 w = *(const float4*)(wb + g*DD);
        acc[g][0] = ffma2(pack2(w.x, w.y), x2, acc[g][0]);
        acc[g][1] = ffma2(pack2(w.z, w.w), x2, acc[g][1]);
    }
}

// grid (32, 19), block 128: b = tid>>2, jl = tid&3, 16 j per gate per block
__global__ __launch_bounds__(128) void k_lstm_mm(
    const float* __restrict__ content, const float* __restrict__ style,
    const float* __restrict__ Wk, const float* __restrict__ Wr, int cur)
{
    int tid = threadIdx.x;
    int b  = tid >> 2;                 // 0..31
    int jl = tid & 3;                  // 0..3
    int j0 = blockIdx.x * 16 + jl * 4; // 4 consecutive output units per gate
    int ch = blockIdx.y;               // K chunk 0..18

    unsigned long long acc[4][2];
    #pragma unroll
    for (int g = 0; g < 4; g++) { acc[g][0] = 0ULL; acc[g][1] = 0ULL; }

    const float* Wb; const float* xp; int n;
    if (ch < 8)       { Wb = Wk + (size_t)(ch*64)*H4 + j0;           xp = g_emb + b*DD + ch*64;              n = 64; }
    else if (ch < 10) { Wb = Wk + (size_t)(512+(ch-8)*64)*H4 + j0;   xp = content + b*128 + (ch-8)*64;       n = 64; }
    else if (ch == 10){ Wb = Wk + (size_t)640*H4 + j0;               xp = style + b*16;                      n = 16; }
    else              { Wb = Wr + (size_t)((ch-11)*64)*H4 + j0;      xp = g_hbuf[cur^1] + b*DD + (ch-11)*64; n = 64; }

    #pragma unroll 4
    for (int k = 0; k < n; k++) fma4p(acc, xp[k], Wb + (size_t)k*H4);

    float* zp = &g_zpart[ch][b][0];
    #pragma unroll
    for (int g = 0; g < 4; g++) {
        float2 a = unpack2(acc[g][0]);
        float2 c = unpack2(acc[g][1]);
        *(float4*)(zp + g*DD + j0) = make_float4(a.x, a.y, c.x, c.y);
    }
}

// ---------- LSTM epilogue: reduce chunks, gates, state update ----------
__global__ __launch_bounds__(512) void k_lstm_fin(const float* __restrict__ bias, int cur) {
    int b = blockIdx.x, j = threadIdx.x;   // grid 32, block 512
    float z0 = bias[j], z1 = bias[DD + j], z2 = bias[2*DD + j], z3 = bias[3*DD + j];
    #pragma unroll
    for (int ch = 0; ch < NCH; ch++) {
        const float* zp = &g_zpart[ch][b][0];
        z0 += zp[j]; z1 += zp[DD + j]; z2 += zp[2*DD + j]; z3 += zp[3*DD + j];
    }
    float iv = sigf(z0), fv = sigf(z1), gv = tanhf(z2), ov = sigf(z3);
    float c = fv * g_cbuf[cur ^ 1][b*DD + j] + iv * gv;
    float h = ov * tanhf(c);
    g_cbuf[cur][b*DD + j] = c;
    g_hbuf[cur][b*DD + j] = h;
    g_hT[j*BB + b] = h;                    // k-major for the logits kernel
}

// ---------- partial logits: one K-quarter per block, no combine ----------
// grid (250 vchunks, 4 kq), block 128: thread = one vocab column, K=128.
__global__ __launch_bounds__(128, 7) void k_zl(const float* __restrict__ Ws)
{
    __shared__ __align__(16) float Hs[128*BB];   // 16KB: one K-quarter of h
    int tid = threadIdx.x;
    int kq = blockIdx.y;
    int v = blockIdx.x * 128 + tid;

    {   // stage H quarter (rows kq*128 .. kq*128+127)
        const float4* src = (const float4*)(g_hT + kq*128*BB);
        float4* dst = (float4*)Hs;
        #pragma unroll
        for (int i = 0; i < 8; i++) dst[tid + 128*i] = src[tid + 128*i];
    }
    __syncthreads();

    unsigned long long acc[16];
    #pragma unroll
    for (int i = 0; i < 16; i++) acc[i] = 0ULL;

    const float* wcol = Ws + (size_t)(kq*128)*VV + v;
    for (int k0 = 0; k0 < 128; k0 += 8) {
        float wsf[8];                                     // 8-deep LDG prefetch
        #pragma unroll
        for (int u = 0; u < 8; u++) wsf[u] = wcol[(size_t)(k0+u) * VV];
        #pragma unroll
        for (int u = 0; u < 8; u++) {
            unsigned long long ws2 = pack2(wsf[u], wsf[u]);
            const ulonglong2* hr = (const ulonglong2*)(Hs + (k0+u)*BB);
            #pragma unroll
            for (int i = 0; i < 8; i++) {
                ulonglong2 q = hr[i];
                acc[2*i]   = ffma2(q.x, ws2, acc[2*i]);   // batches (4i,4i+1)
                acc[2*i+1] = ffma2(q.y, ws2, acc[2*i+1]); // batches (4i+2,4i+3)
            }
        }
    }

    float4* o = (float4*)(g_zl[kq] + (size_t)v*BB);       // acc[j] = batches (2j,2j+1)
    #pragma unroll
    for (int i = 0; i < 8; i++) {
        float2 a = unpack2(acc[2*i]);
        float2 c = unpack2(acc[2*i+1]);
        o[i] = make_float4(a.x, a.y, c.x, c.y);
    }
}

// ---------- sum partials + exp -> g_P, per-block psum ----------
// grid 250, block 128: thread = one vocab column.
__global__ __launch_bounds__(128) void k_exps(const float* __restrict__ bs)
{
    __shared__ float sm[128*33 + 128];     // stash rows + red scratch
    int tid = threadIdx.x;
    int v = blockIdx.x * 128 + tid;

    float w[32];
    {
        const float4* p0 = (const float4*)(g_zl[0] + (size_t)v*BB);
        const float4* p1 = (const float4*)(g_zl[1] + (size_t)v*BB);
        const float4* p2 = (const float4*)(g_zl[2] + (size_t)v*BB);
        const float4* p3 = (const float4*)(g_zl[3] + (size_t)v*BB);
        #pragma unroll
        for (int i = 0; i < 8; i++) {
            float4 a = p0[i], b4 = p1[i], c4 = p2[i], d4 = p3[i];
            w[4*i]   = a.x + b4.x + c4.x + d4.x;
            w[4*i+1] = a.y + b4.y + c4.y + d4.y;
            w[4*i+2] = a.z + b4.z + c4.z + d4.z;
            w[4*i+3] = a.w + b4.w + c4.w + d4.w;
        }
    }
    float bv = bs[v];
    #pragma unroll
    for (int b = 0; b < 32; b++) w[b] = expf(w[b] + bv);  // |logit| small: safe

    float4* pout = (float4*)(g_P + (size_t)v*BB);
    #pragma unroll
    for (int i = 0; i < 8; i++)
        pout[i] = make_float4(w[4*i], w[4*i+1], w[4*i+2], w[4*i+3]);

    float* srow = sm + tid*33;
    #pragma unroll
    for (int b = 0; b < 32; b++) srow[b] = w[b];
    __syncthreads();

    {   // two-stage per-batch sum over 128 vocab (deterministic)
        int b2 = tid & 31, sl = tid >> 5;   // 4 slices
        float s = 0.f;
        #pragma unroll 4
        for (int u = sl; u < 128; u += 4) s += sm[u*33 + b2];
        sm[128*33 + sl*32 + b2] = s;
    }
    __syncthreads();
    if (tid < 32) {
        float s = 0.f;
        #pragma unroll
        for (int i = 0; i < 4; i++) s += sm[128*33 + i*32 + tid];
        g_psum[blockIdx.x*BB + tid] = s;
    }
}

// ---------- partial (exp @ E): grid (250 vchunks, 4 dq), block 128 ----------
// Each thread: 1 d column, 32 batches, 128 vocab rows.
__global__ __launch_bounds__(128, 7) void k_emb(const float* __restrict__ E)
{
    __shared__ __align__(16) float smP[128*BB];  // 16KB: P[128][32]
    int tid = threadIdx.x;
    int v0 = blockIdx.x * 128;
    int d  = blockIdx.y * 128 + tid;

    {
        const float4* src = (const float4*)(g_P + (size_t)v0*BB);
        float4* dst = (float4*)smP;
        #pragma unroll
        for (int i = 0; i < 8; i++) dst[tid + 128*i] = src[tid + 128*i];
    }
    __syncthreads();

    unsigned long long acc[16];
    #pragma unroll
    for (int i = 0; i < 16; i++) acc[i] = 0ULL;

    const float* ecol = E + (size_t)v0*DD + d;
    for (int vv0 = 0; vv0 < 128; vv0 += 8) {
        float ef[8];                                      // 8-deep LDG prefetch
        #pragma unroll
        for (int u = 0; u < 8; u++) ef[u] = ecol[(size_t)(vv0+u) * DD];
        #pragma unroll
        for (int u = 0; u < 8; u++) {
            unsigned long long e2 = pack2(ef[u], ef[u]);
            const ulonglong2* wr = (const ulonglong2*)(smP + (vv0+u)*BB);
            #pragma unroll
            for (int i = 0; i < 8; i++) {
                ulonglong2 q = wr[i];
                acc[2*i]   = ffma2(q.x, e2, acc[2*i]);
                acc[2*i+1] = ffma2(q.y, e2, acc[2*i+1]);
            }
        }
    }

    int pc = blockIdx.x;                   // 0..249 partial chunk
    float* ob = g_acc + ((size_t)pc*BB)*DD + d;
    #pragma unroll
    for (int i = 0; i < 16; i++) {         // acc[i] = batches (2i,2i+1)
        float2 t = unpack2(acc[i]);
        ob[(size_t)(2*i)  *DD] = t.x;
        ob[(size_t)(2*i+1)*DD] = t.y;
    }
}

// ---------- final reduce: normalize soft embedding, write output ----------
// grid (32 b, 8 dgroups), block 256 (8 slices x 32 float2 lanes)
__global__ __launch_bounds__(256) void k_reduce(float* __restrict__ out, int t) {
    __shared__ float2 red[8][32];
    __shared__ float s_inv;
    int b = blockIdx.x, dg = blockIdx.y;
    int tid = threadIdx.x;
    int s = tid >> 5, d2l = tid & 31;

    float2 a = make_float2(0.f, 0.f);
    const float2* gin = (const float2*)g_acc;
    for (int c = s; c < NVB; c += 8) {
        float2 p = gin[((size_t)c*BB + b)*(DD/2) + dg*32 + d2l];
        a.x += p.x; a.y += p.y;
    }
    red[s][d2l] = a;

    if (tid < 32) {                        // deterministic softmax denominator
        float ts = 0.f;
        for (int c = tid; c < NVB; c += 32) ts += g_psum[c*BB + b];
        #pragma unroll
        for (int o = 16; o > 0; o >>= 1) ts += __shfl_xor_sync(0xffffffffu, ts, o);
        if (tid == 0) s_inv = 1.0f / ts;
    }
    __syncthreads();

    if (s == 0) {
        #pragma unroll
        for (int i = 1; i < 8; i++) { a.x += red[i][d2l].x; a.y += red[i][d2l].y; }
        float inv = s_inv;
        a.x *= inv; a.y *= inv;
        int d2 = dg*32 + d2l;
        ((float2*)g_emb)[b*(DD/2) + d2] = a;
        ((float2*)out)[((size_t)b*TT + t)*(DD/2) + d2] = a;
    }
}

extern "C" void kernel_launch(void* const* d_in, const int* in_sizes, int n_in,
                              void* d_out, int out_size) {
    const float* content = (const float*)d_in[0];
    const float* style   = (const float*)d_in[1];
    const float* E       = (const float*)d_in[2];
    const float* Wk      = (const float*)d_in[3];
    const float* Wr      = (const float*)d_in[4];
    const float* bias    = (const float*)d_in[5];
    const float* Ws      = (const float*)d_in[6];
    const float* bs      = (const float*)d_in[7];
    float* out = (float*)d_out;

    k_init<<<BB, DD>>>(E, out);
    for (int t = 1; t < TT; t++) {
        int cur = t & 1;
        k_lstm_mm<<<dim3(32, NCH), 128>>>(content, style, Wk, Wr, cur);
        k_lstm_fin<<<BB, DD>>>(bias, cur);
        k_zl<<<dim3(NVB, 4), 128>>>(Ws);
        k_exps<<<NVB, 128>>>(bs);
        k_emb<<<dim3(NVB, 4), 128>>>(E);
        k_reduce<<<dim3(BB, 8), 256>>>(out, t);
    }
}

// round 9
// speedup vs baseline: 2.4723x; 1.0240x over previous
#include <cuda_runtime.h>
#include <math.h>

// Problem constants (fixed by reference)
#define BB     32          // batch
#define TT     64          // timesteps
#define DD     512         // d_emb / LSTM units
#define H4     2048        // 4 * units
#define VV     32000       // vocab
#define NCH    19          // LSTM K chunks (8 emb + 2 content + 1 style + 8 h)
#define NVB    250         // vocab blocks of 128 (psum / emb partial chunks)

// Persistent device state / scratch (no allocations allowed)
__device__ __align__(16) float g_hbuf[2][BB*DD];
__device__ __align__(16) float g_cbuf[2][BB*DD];
__device__ __align__(16) float g_hT[DD*BB];          // h in [k][b] layout
__device__ __align__(16) float g_emb[BB*DD];         // current soft embedding
__device__ __align__(16) float g_zpart[NCH][BB][H4]; // LSTM gate partials
__device__ __align__(16) float g_zl[4][VV*BB];       // logit K-quarter partials
__device__ __align__(16) float g_P[VV*BB];           // exp(logits), [v][b]
__device__ __align__(16) float g_acc[(size_t)NVB*BB*DD]; // weighted-E partials
__device__ __align__(16) float g_psum[NVB*BB];       // exp partial sums

// ---------- packed f32x2 helpers ----------
static __device__ __forceinline__ unsigned long long ffma2(unsigned long long a,
                                                           unsigned long long b,
                                                           unsigned long long c) {
    unsigned long long d;
    asm("fma.rn.f32x2 %0, %1, %2, %3;" : "=l"(d) : "l"(a), "l"(b), "l"(c));
    return d;
}
static __device__ __forceinline__ unsigned long long pack2(float x, float y) {
    unsigned long long r;
    asm("mov.b64 %0, {%1, %2};" : "=l"(r) : "f"(x), "f"(y));
    return r;
}
static __device__ __forceinline__ float2 unpack2(unsigned long long v) {
    float2 r;
    asm("mov.b64 {%0, %1}, %2;" : "=f"(r.x), "=f"(r.y) : "l"(v));
    return r;
}
static __device__ __forceinline__ float sigf(float x) { return 1.0f / (1.0f + expf(-x)); }

// ---------- t = 0: SOS embedding, zero state ----------
__global__ void k_init(const float* __restrict__ E, float* __restrict__ out) {
    int b = blockIdx.x, d = threadIdx.x;       // grid 32, block 512
    float e = E[d];                            // E[SOS=0][d]
    g_emb[b*DD + d] = e;
    out[(size_t)(b*TT)*DD + d] = e;
    g_hbuf[0][b*DD + d] = 0.f;
    g_cbuf[0][b*DD + d] = 0.f;
}

// ---------- LSTM gate GEMM, K-split partials (chunks of 64) ----------
static __device__ __forceinline__ void fma4p(unsigned long long (&acc)[4][2],
                                             float x, const float* wb) {
    unsigned long long x2 = pack2(x, x);
    #pragma unroll
    for (int g = 0; g < 4; g++) {
        float4 w = *(const float4*)(wb + g*DD);
        acc[g][0] = ffma2(pack2(w.x, w.y), x2, acc[g][0]);
        acc[g][1] = ffma2(pack2(w.z, w.w), x2, acc[g][1]);
    }
}

// grid (32, 19), block 128: b = tid>>2, jl = tid&3, 16 j per gate per block
__global__ __launch_bounds__(128) void k_lstm_mm(
    const float* __restrict__ content, const float* __restrict__ style,
    const float* __restrict__ Wk, const float* __restrict__ Wr, int cur)
{
    int tid = threadIdx.x;
    int b  = tid >> 2;                 // 0..31
    int jl = tid & 3;                  // 0..3
    int j0 = blockIdx.x * 16 + jl * 4; // 4 consecutive output units per gate
    int ch = blockIdx.y;               // K chunk 0..18

    unsigned long long acc[4][2];
    #pragma unroll
    for (int g = 0; g < 4; g++) { acc[g][0] = 0ULL; acc[g][1] = 0ULL; }

    const float* Wb; const float* xp; int n;
    if (ch < 8)       { Wb = Wk + (size_t)(ch*64)*H4 + j0;           xp = g_emb + b*DD + ch*64;              n = 64; }
    else if (ch < 10) { Wb = Wk + (size_t)(512+(ch-8)*64)*H4 + j0;   xp = content + b*128 + (ch-8)*64;       n = 64; }
    else if (ch == 10){ Wb = Wk + (size_t)640*H4 + j0;               xp = style + b*16;                      n = 16; }
    else              { Wb = Wr + (size_t)((ch-11)*64)*H4 + j0;      xp = g_hbuf[cur^1] + b*DD + (ch-11)*64; n = 64; }

    #pragma unroll 4
    for (int k = 0; k < n; k++) fma4p(acc, xp[k], Wb + (size_t)k*H4);

    float* zp = &g_zpart[ch][b][0];
    #pragma unroll
    for (int g = 0; g < 4; g++) {
        float2 a = unpack2(acc[g][0]);
        float2 c = unpack2(acc[g][1]);
        *(float4*)(zp + g*DD + j0) = make_float4(a.x, a.y, c.x, c.y);
    }
}

// ---------- LSTM epilogue: reduce chunks, gates, state update ----------
__global__ __launch_bounds__(512) void k_lstm_fin(const float* __restrict__ bias, int cur) {
    int b = blockIdx.x, j = threadIdx.x;   // grid 32, block 512
    float z0 = bias[j], z1 = bias[DD + j], z2 = bias[2*DD + j], z3 = bias[3*DD + j];
    #pragma unroll
    for (int ch = 0; ch < NCH; ch++) {
        const float* zp = &g_zpart[ch][b][0];
        z0 += zp[j]; z1 += zp[DD + j]; z2 += zp[2*DD + j]; z3 += zp[3*DD + j];
    }
    float iv = sigf(z0), fv = sigf(z1), gv = tanhf(z2), ov = sigf(z3);
    float c = fv * g_cbuf[cur ^ 1][b*DD + j] + iv * gv;
    float h = ov * tanhf(c);
    g_cbuf[cur][b*DD + j] = c;
    g_hbuf[cur][b*DD + j] = h;
    g_hT[j*BB + b] = h;                    // k-major for the logits kernel
}

// ---------- partial logits: one K-quarter per block, 2 vocab cols/thread ----------
// grid (125 vchunks-of-256, 4 kq), block 128: thread = vocab pair (v, v+1), K=128.
__global__ __launch_bounds__(128) void k_zl(const float* __restrict__ Ws)
{
    __shared__ __align__(16) float Hs[128*BB];   // 16KB: one K-quarter of h
    int tid = threadIdx.x;
    int kq = blockIdx.y;
    int v = blockIdx.x * 256 + tid * 2;

    {   // stage H quarter (rows kq*128 .. kq*128+127)
        const float4* src = (const float4*)(g_hT + kq*128*BB);
        float4* dst = (float4*)Hs;
        #pragma unroll
        for (int i = 0; i < 8; i++) dst[tid + 128*i] = src[tid + 128*i];
    }
    __syncthreads();

    unsigned long long a0[16], a1[16];
    #pragma unroll
    for (int i = 0; i < 16; i++) { a0[i] = 0ULL; a1[i] = 0ULL; }

    const float2* wcol = (const float2*)(Ws + (size_t)(kq*128)*VV + v);
    for (int k0 = 0; k0 < 128; k0 += 4) {
        float2 wf[4];                                     // 4-deep LDG.64 prefetch
        #pragma unroll
        for (int u = 0; u < 4; u++) wf[u] = wcol[(size_t)(k0+u) * (VV/2)];
        #pragma unroll
        for (int u = 0; u < 4; u++) {
            unsigned long long w0 = pack2(wf[u].x, wf[u].x);
            unsigned long long w1 = pack2(wf[u].y, wf[u].y);
            const ulonglong2* hr = (const ulonglong2*)(Hs + (k0+u)*BB);
            #pragma unroll
            for (int i = 0; i < 8; i++) {                 // 1 LDS feeds 4 FFMA2
                ulonglong2 q = hr[i];
                a0[2*i]   = ffma2(q.x, w0, a0[2*i]);      // col v,   batches (4i,4i+1)
                a0[2*i+1] = ffma2(q.y, w0, a0[2*i+1]);    // col v,   batches (4i+2,4i+3)
                a1[2*i]   = ffma2(q.x, w1, a1[2*i]);      // col v+1
                a1[2*i+1] = ffma2(q.y, w1, a1[2*i+1]);
            }
        }
    }

    float4* o0 = (float4*)(g_zl[kq] + (size_t)v*BB);
    float4* o1 = (float4*)(g_zl[kq] + (size_t)(v+1)*BB);
    #pragma unroll
    for (int i = 0; i < 8; i++) {
        float2 x0 = unpack2(a0[2*i]), y0 = unpack2(a0[2*i+1]);
        float2 x1 = unpack2(a1[2*i]), y1 = unpack2(a1[2*i+1]);
        o0[i] = make_float4(x0.x, x0.y, y0.x, y0.y);
        o1[i] = make_float4(x1.x, x1.y, y1.x, y1.y);
    }
}

// ---------- sum partials + exp -> g_P, per-block psum ----------
// grid 250, block 128: thread = one vocab column.
__global__ __launch_bounds__(128) void k_exps(const float* __restrict__ bs)
{
    __shared__ float sm[128*33 + 128];     // stash rows + red scratch
    int tid = threadIdx.x;
    int v = blockIdx.x * 128 + tid;

    float w[32];
    {
        const float4* p0 = (const float4*)(g_zl[0] + (size_t)v*BB);
        const float4* p1 = (const float4*)(g_zl[1] + (size_t)v*BB);
        const float4* p2 = (const float4*)(g_zl[2] + (size_t)v*BB);
        const float4* p3 = (const float4*)(g_zl[3] + (size_t)v*BB);
        #pragma unroll
        for (int i = 0; i < 8; i++) {
            float4 a = p0[i], b4 = p1[i], c4 = p2[i], d4 = p3[i];
            w[4*i]   = a.x + b4.x + c4.x + d4.x;
            w[4*i+1] = a.y + b4.y + c4.y + d4.y;
            w[4*i+2] = a.z + b4.z + c4.z + d4.z;
            w[4*i+3] = a.w + b4.w + c4.w + d4.w;
        }
    }
    float bv = bs[v];
    #pragma unroll
    for (int b = 0; b < 32; b++) w[b] = expf(w[b] + bv);  // |logit| small: safe

    float4* pout = (float4*)(g_P + (size_t)v*BB);
    #pragma unroll
    for (int i = 0; i < 8; i++)
        pout[i] = make_float4(w[4*i], w[4*i+1], w[4*i+2], w[4*i+3]);

    float* srow = sm + tid*33;
    #pragma unroll
    for (int b = 0; b < 32; b++) srow[b] = w[b];
    __syncthreads();

    {   // two-stage per-batch sum over 128 vocab (deterministic)
        int b2 = tid & 31, sl = tid >> 5;   // 4 slices
        float s = 0.f;
        #pragma unroll 4
        for (int u = sl; u < 128; u += 4) s += sm[u*33 + b2];
        sm[128*33 + sl*32 + b2] = s;
    }
    __syncthreads();
    if (tid < 32) {
        float s = 0.f;
        #pragma unroll
        for (int i = 0; i < 4; i++) s += sm[128*33 + i*32 + tid];
        g_psum[blockIdx.x*BB + tid] = s;
    }
}

// ---------- partial (exp @ E): grid (250 vchunks, 2 dhalves), block 128 ----------
// Each thread: d pair (d, d+1), 32 batches, 128 vocab rows.
__global__ __launch_bounds__(128) void k_emb(const float* __restrict__ E)
{
    __shared__ __align__(16) float smP[128*BB];  // 16KB: P[128][32]
    int tid = threadIdx.x;
    int v0 = blockIdx.x * 128;
    int d  = blockIdx.y * 256 + tid * 2;

    {
        const float4* src = (const float4*)(g_P + (size_t)v0*BB);
        float4* dst = (float4*)smP;
        #pragma unroll
        for (int i = 0; i < 8; i++) dst[tid + 128*i] = src[tid + 128*i];
    }
    __syncthreads();

    unsigned long long a0[16], a1[16];
    #pragma unroll
    for (int i = 0; i < 16; i++) { a0[i] = 0ULL; a1[i] = 0ULL; }

    const float2* ecol = (const float2*)(E + (size_t)v0*DD + d);
    for (int vv0 = 0; vv0 < 128; vv0 += 4) {
        float2 ef[4];                                     // 4-deep LDG.64 prefetch
        #pragma unroll
        for (int u = 0; u < 4; u++) ef[u] = ecol[(size_t)(vv0+u) * (DD/2)];
        #pragma unroll
        for (int u = 0; u < 4; u++) {
            unsigned long long e0 = pack2(ef[u].x, ef[u].x);
            unsigned long long e1 = pack2(ef[u].y, ef[u].y);
            const ulonglong2* wr = (const ulonglong2*)(smP + (vv0+u)*BB);
            #pragma unroll
            for (int i = 0; i < 8; i++) {                 // 1 LDS feeds 4 FFMA2
                ulonglong2 q = wr[i];
                a0[2*i]   = ffma2(q.x, e0, a0[2*i]);
                a0[2*i+1] = ffma2(q.y, e0, a0[2*i+1]);
                a1[2*i]   = ffma2(q.x, e1, a1[2*i]);
                a1[2*i+1] = ffma2(q.y, e1, a1[2*i+1]);
            }
        }
    }

    int pc = blockIdx.x;                   // 0..249 partial chunk
    float* ob = g_acc + ((size_t)pc*BB)*DD + d;
    #pragma unroll
    for (int i = 0; i < 16; i++) {         // a*[i] = batches (2i,2i+1)
        float2 t0 = unpack2(a0[i]);        // column d
        float2 t1 = unpack2(a1[i]);        // column d+1
        *(float2*)(ob + (size_t)(2*i)  *DD) = make_float2(t0.x, t1.x);
        *(float2*)(ob + (size_t)(2*i+1)*DD) = make_float2(t0.y, t1.y);
    }
}

// ---------- final reduce: normalize soft embedding, write output ----------
// grid (32 b, 8 dgroups), block 256 (8 slices x 32 float2 lanes)
__global__ __launch_bounds__(256) void k_reduce(float* __restrict__ out, int t) {
    __shared__ float2 red[8][32];
    __shared__ float s_inv;
    int b = blockIdx.x, dg = blockIdx.y;
    int tid = threadIdx.x;
    int s = tid >> 5, d2l = tid & 31;

    float2 a = make_float2(0.f, 0.f);
    const float2* gin = (const float2*)g_acc;
    for (int c = s; c < NVB; c += 8) {
        float2 p = gin[((size_t)c*BB + b)*(DD/2) + dg*32 + d2l];
        a.x += p.x; a.y += p.y;
    }
    red[s][d2l] = a;

    if (tid < 32) {                        // deterministic softmax denominator
        float ts = 0.f;
        for (int c = tid; c < NVB; c += 32) ts += g_psum[c*BB + b];
        #pragma unroll
        for (int o = 16; o > 0; o >>= 1) ts += __shfl_xor_sync(0xffffffffu, ts, o);
        if (tid == 0) s_inv = 1.0f / ts;
    }
    __syncthreads();

    if (s == 0) {
        #pragma unroll
        for (int i = 1; i < 8; i++) { a.x += red[i][d2l].x; a.y += red[i][d2l].y; }
        float inv = s_inv;
        a.x *= inv; a.y *= inv;
        int d2 = dg*32 + d2l;
        ((float2*)g_emb)[b*(DD/2) + d2] = a;
        ((float2*)out)[((size_t)b*TT + t)*(DD/2) + d2] = a;
    }
}

extern "C" void kernel_launch(void* const* d_in, const int* in_sizes, int n_in,
                              void* d_out, int out_size) {
    const float* content = (const float*)d_in[0];
    const float* style   = (const float*)d_in[1];
    const float* E       = (const float*)d_in[2];
    const float* Wk      = (const float*)d_in[3];
    const float* Wr      = (const float*)d_in[4];
    const float* bias    = (const float*)d_in[5];
    const float* Ws      = (const float*)d_in[6];
    const float* bs      = (const float*)d_in[7];
    float* out = (float*)d_out;

    k_init<<<BB, DD>>>(E, out);
    for (int t = 1; t < TT; t++) {
        int cur = t & 1;
        k_lstm_mm<<<dim3(32, NCH), 128>>>(content, style, Wk, Wr, cur);
        k_lstm_fin<<<BB, DD>>>(bias, cur);
        k_zl<<<dim3(125, 4), 128>>>(Ws);
        k_exps<<<NVB, 128>>>(bs);
        k_emb<<<dim3(NVB, 2), 128>>>(E);
        k_reduce<<<dim3(BB, 8), 256>>>(out, t);
    }
}

// round 10
// speedup vs baseline: 2.5491x; 1.0310x over previous
#include <cuda_runtime.h>
#include <math.h>

// Problem constants (fixed by reference)
#define BB     32          // batch
#define TT     64          // timesteps
#define DD     512         // d_emb / LSTM units
#define H4     2048        // 4 * units
#define VV     32000       // vocab
#define NCH    19          // LSTM K chunks (8 emb + 2 content + 1 style + 8 h)
#define NVB    250         // g_acc partial chunks (128 vocab each)
#define NPB    500         // psum partial blocks (64 vocab each)

// Persistent device state / scratch (no allocations allowed)
__device__ __align__(16) float g_hbuf[2][BB*DD];
__device__ __align__(16) float g_cbuf[2][BB*DD];
__device__ __align__(16) float g_hT[DD*BB];          // h in [k][b] layout
__device__ __align__(16) float g_emb[BB*DD];         // current soft embedding
__device__ __align__(16) float g_zpart[NCH][BB][H4]; // LSTM gate partials
__device__ __align__(16) float g_zl[4][VV*BB];       // logit K-quarter partials
__device__ __align__(16) float g_P[VV*BB];           // exp(logits), [v][b]
__device__ __align__(16) float g_acc[(size_t)NVB*BB*DD]; // weighted-E partials
__device__ __align__(16) float g_psum[NPB*BB];       // exp partial sums

// ---------- packed f32x2 helpers ----------
static __device__ __forceinline__ unsigned long long ffma2(unsigned long long a,
                                                           unsigned long long b,
                                                           unsigned long long c) {
    unsigned long long d;
    asm("fma.rn.f32x2 %0, %1, %2, %3;" : "=l"(d) : "l"(a), "l"(b), "l"(c));
    return d;
}
static __device__ __forceinline__ unsigned long long pack2(float x, float y) {
    unsigned long long r;
    asm("mov.b64 %0, {%1, %2};" : "=l"(r) : "f"(x), "f"(y));
    return r;
}
static __device__ __forceinline__ float2 unpack2(unsigned long long v) {
    float2 r;
    asm("mov.b64 {%0, %1}, %2;" : "=f"(r.x), "=f"(r.y) : "l"(v));
    return r;
}
static __device__ __forceinline__ float sigf(float x) { return 1.0f / (1.0f + expf(-x)); }

// ---------- t = 0: SOS embedding, zero state ----------
__global__ void k_init(const float* __restrict__ E, float* __restrict__ out) {
    int b = blockIdx.x, d = threadIdx.x;       // grid 32, block 512
    float e = E[d];                            // E[SOS=0][d]
    g_emb[b*DD + d] = e;
    out[(size_t)(b*TT)*DD + d] = e;
    g_hbuf[0][b*DD + d] = 0.f;
    g_cbuf[0][b*DD + d] = 0.f;
}

// ---------- LSTM gate GEMM, K-split partials (chunks of 64) ----------
static __device__ __forceinline__ void fma4p(unsigned long long (&acc)[4][2],
                                             float x, const float* wb) {
    unsigned long long x2 = pack2(x, x);
    #pragma unroll
    for (int g = 0; g < 4; g++) {
        float4 w = *(const float4*)(wb + g*DD);
        acc[g][0] = ffma2(pack2(w.x, w.y), x2, acc[g][0]);
        acc[g][1] = ffma2(pack2(w.z, w.w), x2, acc[g][1]);
    }
}

// grid (32, 19), block 128: b = tid>>2, jl = tid&3, 16 j per gate per block
__global__ __launch_bounds__(128) void k_lstm_mm(
    const float* __restrict__ content, const float* __restrict__ style,
    const float* __restrict__ Wk, const float* __restrict__ Wr, int cur)
{
    int tid = threadIdx.x;
    int b  = tid >> 2;                 // 0..31
    int jl = tid & 3;                  // 0..3
    int j0 = blockIdx.x * 16 + jl * 4; // 4 consecutive output units per gate
    int ch = blockIdx.y;               // K chunk 0..18

    unsigned long long acc[4][2];
    #pragma unroll
    for (int g = 0; g < 4; g++) { acc[g][0] = 0ULL; acc[g][1] = 0ULL; }

    const float* Wb; const float* xp; int n;
    if (ch < 8)       { Wb = Wk + (size_t)(ch*64)*H4 + j0;           xp = g_emb + b*DD + ch*64;              n = 64; }
    else if (ch < 10) { Wb = Wk + (size_t)(512+(ch-8)*64)*H4 + j0;   xp = content + b*128 + (ch-8)*64;       n = 64; }
    else if (ch == 10){ Wb = Wk + (size_t)640*H4 + j0;               xp = style + b*16;                      n = 16; }
    else              { Wb = Wr + (size_t)((ch-11)*64)*H4 + j0;      xp = g_hbuf[cur^1] + b*DD + (ch-11)*64; n = 64; }

    #pragma unroll 4
    for (int k = 0; k < n; k++) fma4p(acc, xp[k], Wb + (size_t)k*H4);

    float* zp = &g_zpart[ch][b][0];
    #pragma unroll
    for (int g = 0; g < 4; g++) {
        float2 a = unpack2(acc[g][0]);
        float2 c = unpack2(acc[g][1]);
        *(float4*)(zp + g*DD + j0) = make_float4(a.x, a.y, c.x, c.y);
    }
}

// ---------- LSTM epilogue: reduce chunks, gates, state update ----------
__global__ __launch_bounds__(512) void k_lstm_fin(const float* __restrict__ bias, int cur) {
    int b = blockIdx.x, j = threadIdx.x;   // grid 32, block 512
    float z0 = bias[j], z1 = bias[DD + j], z2 = bias[2*DD + j], z3 = bias[3*DD + j];
    #pragma unroll
    for (int ch = 0; ch < NCH; ch++) {
        const float* zp = &g_zpart[ch][b][0];
        z0 += zp[j]; z1 += zp[DD + j]; z2 += zp[2*DD + j]; z3 += zp[3*DD + j];
    }
    float iv = sigf(z0), fv = sigf(z1), gv = tanhf(z2), ov = sigf(z3);
    float c = fv * g_cbuf[cur ^ 1][b*DD + j] + iv * gv;
    float h = ov * tanhf(c);
    g_cbuf[cur][b*DD + j] = c;
    g_hbuf[cur][b*DD + j] = h;
    g_hT[j*BB + b] = h;                    // k-major for the logits kernel
}

// ---------- partial logits: one K-quarter per block, 4 cols x 8 batches/thread ----------
// grid (250, 4 kq), block 128: tid = cl(0..31) + 32*bq(0..3).
// Thread: cols v..v+3 (v = bx*128 + cl*4), batches bq*8..bq*8+7, K=128.
__global__ __launch_bounds__(128) void k_zl(const float* __restrict__ Ws)
{
    __shared__ __align__(16) float Hs[128*BB];   // 16KB: one K-quarter of h, [k][b]
    int tid = threadIdx.x;
    int cl = tid & 31, bq = tid >> 5;
    int kq = blockIdx.y;
    int v = blockIdx.x * 128 + cl * 4;

    {   // stage H quarter (rows kq*128 .. +127)
        const float4* src = (const float4*)g_hT + kq*1024;
        float4* dst = (float4*)Hs;
        #pragma unroll
        for (int i = 0; i < 8; i++) dst[tid + 128*i] = src[tid + 128*i];
    }
    __syncthreads();

    unsigned long long a[4][4];                  // [col][batch-pair]
    #pragma unroll
    for (int c = 0; c < 4; c++)
        #pragma unroll
        for (int i = 0; i < 4; i++) a[c][i] = 0ULL;

    const float4* wcol = (const float4*)(Ws + (size_t)(kq*128)*VV + v);
    for (int k0 = 0; k0 < 128; k0 += 4) {
        float4 wf[4];                            // 4-deep LDG.128 prefetch
        #pragma unroll
        for (int u = 0; u < 4; u++) wf[u] = wcol[(size_t)(k0+u) * (VV/4)];
        #pragma unroll
        for (int u = 0; u < 4; u++) {
            unsigned long long w0 = pack2(wf[u].x, wf[u].x);
            unsigned long long w1 = pack2(wf[u].y, wf[u].y);
            unsigned long long w2 = pack2(wf[u].z, wf[u].z);
            unsigned long long w3 = pack2(wf[u].w, wf[u].w);
            const ulonglong2* hr = (const ulonglong2*)(Hs + (k0+u)*BB + bq*8);
            ulonglong2 q0 = hr[0], q1 = hr[1];   // 2 broadcast LDS.128 feed 16 FFMA2
            a[0][0]=ffma2(q0.x,w0,a[0][0]); a[0][1]=ffma2(q0.y,w0,a[0][1]);
            a[0][2]=ffma2(q1.x,w0,a[0][2]); a[0][3]=ffma2(q1.y,w0,a[0][3]);
            a[1][0]=ffma2(q0.x,w1,a[1][0]); a[1][1]=ffma2(q0.y,w1,a[1][1]);
            a[1][2]=ffma2(q1.x,w1,a[1][2]); a[1][3]=ffma2(q1.y,w1,a[1][3]);
            a[2][0]=ffma2(q0.x,w2,a[2][0]); a[2][1]=ffma2(q0.y,w2,a[2][1]);
            a[2][2]=ffma2(q1.x,w2,a[2][2]); a[2][3]=ffma2(q1.y,w2,a[2][3]);
            a[3][0]=ffma2(q0.x,w3,a[3][0]); a[3][1]=ffma2(q0.y,w3,a[3][1]);
            a[3][2]=ffma2(q1.x,w3,a[3][2]); a[3][3]=ffma2(q1.y,w3,a[3][3]);
        }
    }

    #pragma unroll
    for (int c = 0; c < 4; c++) {                // col v+c, batches bq*8..+7
        float2 p0 = unpack2(a[c][0]), p1 = unpack2(a[c][1]);
        float2 p2 = unpack2(a[c][2]), p3 = unpack2(a[c][3]);
        float4* o = (float4*)(g_zl[kq] + (size_t)(v+c)*BB + bq*8);
        o[0] = make_float4(p0.x, p0.y, p1.x, p1.y);
        o[1] = make_float4(p2.x, p2.y, p3.x, p3.y);
    }
}

// ---------- sum partials + exp -> g_P, per-block psum ----------
// grid 500, block 128: tid = vl(0..63) + 64*bh(0..1); thread = v, 16 batches.
__global__ __launch_bounds__(128) void k_exps(const float* __restrict__ bs)
{
    __shared__ float sm[64*33 + 128];      // stash rows + red scratch
    int tid = threadIdx.x;
    int vl = tid & 63, bh = tid >> 6;
    int v = blockIdx.x * 64 + vl;
    int boff = bh * 16;

    float w[16];
    #pragma unroll
    for (int j = 0; j < 16; j++) w[j] = 0.f;
    #pragma unroll
    for (int q = 0; q < 4; q++) {
        const float4* p = (const float4*)(g_zl[q] + (size_t)v*BB + boff);
        #pragma unroll
        for (int i = 0; i < 4; i++) {
            float4 x = p[i];
            w[4*i] += x.x; w[4*i+1] += x.y; w[4*i+2] += x.z; w[4*i+3] += x.w;
        }
    }
    float bv = bs[v];
    #pragma unroll
    for (int j = 0; j < 16; j++) w[j] = expf(w[j] + bv);  // |logit| small: safe

    float4* pout = (float4*)(g_P + (size_t)v*BB + boff);
    #pragma unroll
    for (int i = 0; i < 4; i++)
        pout[i] = make_float4(w[4*i], w[4*i+1], w[4*i+2], w[4*i+3]);

    float* srow = sm + vl*33 + boff;
    #pragma unroll
    for (int j = 0; j < 16; j++) srow[j] = w[j];
    __syncthreads();

    {   // two-stage per-batch sum over 64 vocab (deterministic)
        int b2 = tid & 31, sl = tid >> 5;   // 4 slices
        float s = 0.f;
        #pragma unroll 4
        for (int u = sl; u < 64; u += 4) s += sm[u*33 + b2];
        sm[64*33 + sl*32 + b2] = s;
    }
    __syncthreads();
    if (tid < 32) {
        float s = 0.f;
        #pragma unroll
        for (int i = 0; i < 4; i++) s += sm[64*33 + i*32 + tid];
        g_psum[blockIdx.x*BB + tid] = s;
    }
}

// ---------- partial (exp @ E): grid (250 vchunks, 4 dq), block 128 ----------
// tid = cl(0..31) + 32*bq(0..3). Thread: d..d+3 (d = dq*128 + cl*4), batches bq*8..+7.
__global__ __launch_bounds__(128) void k_emb(const float* __restrict__ E)
{
    __shared__ __align__(16) float smP[128*BB];  // 16KB: P[128][32]
    int tid = threadIdx.x;
    int cl = tid & 31, bq = tid >> 5;
    int v0 = blockIdx.x * 128;
    int d  = blockIdx.y * 128 + cl * 4;

    {
        const float4* src = (const float4*)g_P + (size_t)v0*8;
        float4* dst = (float4*)smP;
        #pragma unroll
        for (int i = 0; i < 8; i++) dst[tid + 128*i] = src[tid + 128*i];
    }
    __syncthreads();

    unsigned long long a[4][4];                  // [d-col][batch-pair]
    #pragma unroll
    for (int c = 0; c < 4; c++)
        #pragma unroll
        for (int i = 0; i < 4; i++) a[c][i] = 0ULL;

    const float4* ecol = (const float4*)(E + (size_t)v0*DD + d);
    for (int vv0 = 0; vv0 < 128; vv0 += 4) {
        float4 ef[4];                            // 4-deep LDG.128 prefetch
        #pragma unroll
        for (int u = 0; u < 4; u++) ef[u] = ecol[(size_t)(vv0+u) * (DD/4)];
        #pragma unroll
        for (int u = 0; u < 4; u++) {
            unsigned long long e0 = pack2(ef[u].x, ef[u].x);
            unsigned long long e1 = pack2(ef[u].y, ef[u].y);
            unsigned long long e2 = pack2(ef[u].z, ef[u].z);
            unsigned long long e3 = pack2(ef[u].w, ef[u].w);
            const ulonglong2* wr = (const ulonglong2*)(smP + (vv0+u)*BB + bq*8);
            ulonglong2 q0 = wr[0], q1 = wr[1];   // 2 broadcast LDS.128 feed 16 FFMA2
            a[0][0]=ffma2(q0.x,e0,a[0][0]); a[0][1]=ffma2(q0.y,e0,a[0][1]);
            a[0][2]=ffma2(q1.x,e0,a[0][2]); a[0][3]=ffma2(q1.y,e0,a[0][3]);
            a[1][0]=ffma2(q0.x,e1,a[1][0]); a[1][1]=ffma2(q0.y,e1,a[1][1]);
            a[1][2]=ffma2(q1.x,e1,a[1][2]); a[1][3]=ffma2(q1.y,e1,a[1][3]);
            a[2][0]=ffma2(q0.x,e2,a[2][0]); a[2][1]=ffma2(q0.y,e2,a[2][1]);
            a[2][2]=ffma2(q1.x,e2,a[2][2]); a[2][3]=ffma2(q1.y,e2,a[2][3]);
            a[3][0]=ffma2(q0.x,e3,a[3][0]); a[3][1]=ffma2(q0.y,e3,a[3][1]);
            a[3][2]=ffma2(q1.x,e3,a[3][2]); a[3][3]=ffma2(q1.y,e3,a[3][3]);
        }
    }

    int pc = blockIdx.x;                   // 0..249 partial chunk
    float* ob = g_acc + ((size_t)pc*BB)*DD + d;
    #pragma unroll
    for (int i = 0; i < 4; i++) {          // rows bq*8+2i, bq*8+2i+1
        float2 t0 = unpack2(a[0][i]), t1 = unpack2(a[1][i]);
        float2 t2 = unpack2(a[2][i]), t3 = unpack2(a[3][i]);
        *(float4*)(ob + (size_t)(bq*8 + 2*i    )*DD) = make_float4(t0.x, t1.x, t2.x, t3.x);
        *(float4*)(ob + (size_t)(bq*8 + 2*i + 1)*DD) = make_float4(t0.y, t1.y, t2.y, t3.y);
    }
}

// ---------- final reduce: normalize soft embedding, write output ----------
// grid (32 b, 8 dgroups), block 256 (8 slices x 32 float2 lanes)
__global__ __launch_bounds__(256) void k_reduce(float* __restrict__ out, int t) {
    __shared__ float2 red[8][32];
    __shared__ float s_inv;
    int b = blockIdx.x, dg = blockIdx.y;
    int tid = threadIdx.x;
    int s = tid >> 5, d2l = tid & 31;

    float2 a = make_float2(0.f, 0.f);
    const float2* gin = (const float2*)g_acc;
    for (int c = s; c < NVB; c += 8) {
        float2 p = gin[((size_t)c*BB + b)*(DD/2) + dg*32 + d2l];
        a.x += p.x; a.y += p.y;
    }
    red[s][d2l] = a;

    if (tid < 32) {                        // deterministic softmax denominator
        float ts = 0.f;
        for (int c = tid; c < NPB; c += 32) ts += g_psum[c*BB + b];
        #pragma unroll
        for (int o = 16; o > 0; o >>= 1) ts += __shfl_xor_sync(0xffffffffu, ts, o);
        if (tid == 0) s_inv = 1.0f / ts;
    }
    __syncthreads();

    if (s == 0) {
        #pragma unroll
        for (int i = 1; i < 8; i++) { a.x += red[i][d2l].x; a.y += red[i][d2l].y; }
        float inv = s_inv;
        a.x *= inv; a.y *= inv;
        int d2 = dg*32 + d2l;
        ((float2*)g_emb)[b*(DD/2) + d2] = a;
        ((float2*)out)[((size_t)b*TT + t)*(DD/2) + d2] = a;
    }
}

extern "C" void kernel_launch(void* const* d_in, const int* in_sizes, int n_in,
                              void* d_out, int out_size) {
    const float* content = (const float*)d_in[0];
    const float* style   = (const float*)d_in[1];
    const float* E       = (const float*)d_in[2];
    const float* Wk      = (const float*)d_in[3];
    const float* Wr      = (const float*)d_in[4];
    const float* bias    = (const float*)d_in[5];
    const float* Ws      = (const float*)d_in[6];
    const float* bs      = (const float*)d_in[7];
    float* out = (float*)d_out;

    k_init<<<BB, DD>>>(E, out);
    for (int t = 1; t < TT; t++) {
        int cur = t & 1;
        k_lstm_mm<<<dim3(32, NCH), 128>>>(content, style, Wk, Wr, cur);
        k_lstm_fin<<<BB, DD>>>(bias, cur);
        k_zl<<<dim3(250, 4), 128>>>(Ws);
        k_exps<<<NPB, 128>>>(bs);
        k_emb<<<dim3(250, 4), 128>>>(E);
        k_reduce<<<dim3(BB, 8), 256>>>(out, t);
    }
}

// round 11
// speedup vs baseline: 2.8784x; 1.1292x over previous
#include <cuda_runtime.h>
#include <math.h>

// Problem constants (fixed by reference)
#define BB     32          // batch
#define TT     64          // timesteps
#define DD     512         // d_emb / LSTM units
#define H4     2048        // 4 * units
#define VV     32000       // vocab
#define NCH    19          // LSTM K chunks (8 emb + 2 content + 1 style + 8 h)
#define NVB    250         // g_acc partial chunks (128 vocab each)
#define NPB    500         // psum partial blocks (64 vocab each)

// Persistent device state / scratch (no allocations allowed)
__device__ __align__(16) float g_hbuf[2][BB*DD];
__device__ __align__(16) float g_cbuf[2][BB*DD];
__device__ __align__(16) float g_hT[DD*BB];          // h in [k][b] layout
__device__ __align__(16) float g_emb[BB*DD];         // current soft embedding
__device__ __align__(16) float g_zpart[NCH][BB][H4]; // LSTM gate partials
__device__ __align__(16) float g_zl[4][VV*BB];       // logit K-quarter partials
__device__ __align__(16) float g_P[VV*BB];           // exp(logits), [v][b]
__device__ __align__(16) float g_acc[(size_t)NVB*BB*DD]; // weighted-E partials
__device__ __align__(16) float g_psum[NPB*BB];       // exp partial sums

// ---------- packed f32x2 helpers ----------
static __device__ __forceinline__ unsigned long long ffma2(unsigned long long a,
                                                           unsigned long long b,
                                                           unsigned long long c) {
    unsigned long long d;
    asm("fma.rn.f32x2 %0, %1, %2, %3;" : "=l"(d) : "l"(a), "l"(b), "l"(c));
    return d;
}
static __device__ __forceinline__ unsigned long long pack2(float x, float y) {
    unsigned long long r;
    asm("mov.b64 %0, {%1, %2};" : "=l"(r) : "f"(x), "f"(y));
    return r;
}
static __device__ __forceinline__ float2 unpack2(unsigned long long v) {
    float2 r;
    asm("mov.b64 {%0, %1}, %2;" : "=f"(r.x), "=f"(r.y) : "l"(v));
    return r;
}
static __device__ __forceinline__ float sigf(float x) { return 1.0f / (1.0f + expf(-x)); }

// ---------- cp.async (LDGSTS) helpers ----------
static __device__ __forceinline__ unsigned sptr(const void* p) {
    return (unsigned)__cvta_generic_to_shared(p);
}
static __device__ __forceinline__ void cp16(unsigned dst, const void* src) {
    asm volatile("cp.async.cg.shared.global [%0], [%1], 16;\n" :: "r"(dst), "l"(src));
}
static __device__ __forceinline__ void cp_commit() {
    asm volatile("cp.async.commit_group;\n" ::: "memory");
}
static __device__ __forceinline__ void cp_wait1() {
    asm volatile("cp.async.wait_group 1;\n" ::: "memory");
}

// ---------- t = 0: SOS embedding, zero state ----------
__global__ void k_init(const float* __restrict__ E, float* __restrict__ out) {
    int b = blockIdx.x, d = threadIdx.x;       // grid 32, block 512
    float e = E[d];                            // E[SOS=0][d]
    g_emb[b*DD + d] = e;
    out[(size_t)(b*TT)*DD + d] = e;
    g_hbuf[0][b*DD + d] = 0.f;
    g_cbuf[0][b*DD + d] = 0.f;
}

// ---------- LSTM gate GEMM, K-split partials (chunks of 64) ----------
static __device__ __forceinline__ void fma4p(unsigned long long (&acc)[4][2],
                                             float x, const float* wb) {
    unsigned long long x2 = pack2(x, x);
    #pragma unroll
    for (int g = 0; g < 4; g++) {
        float4 w = *(const float4*)(wb + g*DD);
        acc[g][0] = ffma2(pack2(w.x, w.y), x2, acc[g][0]);
        acc[g][1] = ffma2(pack2(w.z, w.w), x2, acc[g][1]);
    }
}

// grid (32, 19), block 128: b = tid>>2, jl = tid&3, 16 j per gate per block
__global__ __launch_bounds__(128) void k_lstm_mm(
    const float* __restrict__ content, const float* __restrict__ style,
    const float* __restrict__ Wk, const float* __restrict__ Wr, int cur)
{
    int tid = threadIdx.x;
    int b  = tid >> 2;                 // 0..31
    int jl = tid & 3;                  // 0..3
    int j0 = blockIdx.x * 16 + jl * 4; // 4 consecutive output units per gate
    int ch = blockIdx.y;               // K chunk 0..18

    unsigned long long acc[4][2];
    #pragma unroll
    for (int g = 0; g < 4; g++) { acc[g][0] = 0ULL; acc[g][1] = 0ULL; }

    const float* Wb; const float* xp; int n;
    if (ch < 8)       { Wb = Wk + (size_t)(ch*64)*H4 + j0;           xp = g_emb + b*DD + ch*64;              n = 64; }
    else if (ch < 10) { Wb = Wk + (size_t)(512+(ch-8)*64)*H4 + j0;   xp = content + b*128 + (ch-8)*64;       n = 64; }
    else if (ch == 10){ Wb = Wk + (size_t)640*H4 + j0;               xp = style + b*16;                      n = 16; }
    else              { Wb = Wr + (size_t)((ch-11)*64)*H4 + j0;      xp = g_hbuf[cur^1] + b*DD + (ch-11)*64; n = 64; }

    #pragma unroll 4
    for (int k = 0; k < n; k++) fma4p(acc, xp[k], Wb + (size_t)k*H4);

    float* zp = &g_zpart[ch][b][0];
    #pragma unroll
    for (int g = 0; g < 4; g++) {
        float2 a = unpack2(acc[g][0]);
        float2 c = unpack2(acc[g][1]);
        *(float4*)(zp + g*DD + j0) = make_float4(a.x, a.y, c.x, c.y);
    }
}

// ---------- LSTM epilogue: reduce chunks, gates, state update ----------
__global__ __launch_bounds__(512) void k_lstm_fin(const float* __restrict__ bias, int cur) {
    int b = blockIdx.x, j = threadIdx.x;   // grid 32, block 512
    float z0 = bias[j], z1 = bias[DD + j], z2 = bias[2*DD + j], z3 = bias[3*DD + j];
    #pragma unroll
    for (int ch = 0; ch < NCH; ch++) {
        const float* zp = &g_zpart[ch][b][0];
        z0 += zp[j]; z1 += zp[DD + j]; z2 += zp[2*DD + j]; z3 += zp[3*DD + j];
    }
    float iv = sigf(z0), fv = sigf(z1), gv = tanhf(z2), ov = sigf(z3);
    float c = fv * g_cbuf[cur ^ 1][b*DD + j] + iv * gv;
    float h = ov * tanhf(c);
    g_cbuf[cur][b*DD + j] = c;
    g_hbuf[cur][b*DD + j] = h;
    g_hT[j*BB + b] = h;                    // k-major for the logits kernel
}

// ---------- partial logits: one K-quarter per block, cp.async-pipelined ----------
// grid (250, 4 kq), block 128: tid = cl(0..31) + 32*bq(0..3).
// Thread: cols v..v+3 (v = bx*128 + cl*4), batches bq*8..bq*8+7, K=128 in 16 stages of 8.
__global__ __launch_bounds__(128, 8) void k_zl(const float* __restrict__ Ws)
{
    __shared__ __align__(16) float Hs[128*BB];     // 16KB: one K-quarter of h, [k][b]
    __shared__ __align__(16) float Wt[2][8*128];   // 2x4KB: Ws stage [kk][v-chunk]
    int tid = threadIdx.x;
    int cl = tid & 31, bq = tid >> 5;
    int kq = blockIdx.y;
    int v0 = blockIdx.x * 128;

    const float* wsrc = Ws + (size_t)(kq*128)*VV + v0;

    // issue stage 0 async load (8 k-rows x 128 vocab = 4KB; 2x16B per thread)
    {
        #pragma unroll
        for (int j = 0; j < 2; j++) {
            int c2 = tid + 128*j;
            int kk = c2 >> 5, seg = c2 & 31;
            cp16(sptr(&Wt[0][kk*128 + seg*4]), wsrc + (size_t)kk*VV + seg*4);
        }
        cp_commit();
    }

    {   // stage H quarter (rows kq*128 .. +127) with normal loads meanwhile
        const float4* src = (const float4*)g_hT + kq*1024;
        float4* dst = (float4*)Hs;
        #pragma unroll
        for (int i = 0; i < 8; i++) dst[tid + 128*i] = src[tid + 128*i];
    }

    unsigned long long a[4][4];                    // [col][batch-pair]
    #pragma unroll
    for (int c = 0; c < 4; c++)
        #pragma unroll
        for (int i = 0; i < 4; i++) a[c][i] = 0ULL;

    for (int s = 0; s < 16; s++) {
        if (s + 1 < 16) {                          // issue next stage into other buffer
            float* dst = Wt[(s+1) & 1];
            #pragma unroll
            for (int j = 0; j < 2; j++) {
                int c2 = tid + 128*j;
                int kk = c2 >> 5, seg = c2 & 31;
                cp16(sptr(dst + kk*128 + seg*4),
                     wsrc + (size_t)((s+1)*8 + kk)*VV + seg*4);
            }
        }
        cp_commit();
        cp_wait1();                                // stage s resident
        __syncthreads();                           // visible to all (also covers Hs once)

        const float* wbuf = Wt[s & 1];
        #pragma unroll
        for (int kk = 0; kk < 8; kk++) {
            float4 wf = *(const float4*)(wbuf + kk*128 + cl*4);
            unsigned long long w0 = pack2(wf.x, wf.x);
            unsigned long long w1 = pack2(wf.y, wf.y);
            unsigned long long w2 = pack2(wf.z, wf.z);
            unsigned long long w3 = pack2(wf.w, wf.w);
            const ulonglong2* hr = (const ulonglong2*)(Hs + (s*8 + kk)*BB + bq*8);
            ulonglong2 q0 = hr[0], q1 = hr[1];     // 3 broadcast LDS feed 16 FFMA2
            a[0][0]=ffma2(q0.x,w0,a[0][0]); a[0][1]=ffma2(q0.y,w0,a[0][1]);
            a[0][2]=ffma2(q1.x,w0,a[0][2]); a[0][3]=ffma2(q1.y,w0,a[0][3]);
            a[1][0]=ffma2(q0.x,w1,a[1][0]); a[1][1]=ffma2(q0.y,w1,a[1][1]);
            a[1][2]=ffma2(q1.x,w1,a[1][2]); a[1][3]=ffma2(q1.y,w1,a[1][3]);
            a[2][0]=ffma2(q0.x,w2,a[2][0]); a[2][1]=ffma2(q0.y,w2,a[2][1]);
            a[2][2]=ffma2(q1.x,w2,a[2][2]); a[2][3]=ffma2(q1.y,w2,a[2][3]);
            a[3][0]=ffma2(q0.x,w3,a[3][0]); a[3][1]=ffma2(q0.y,w3,a[3][1]);
            a[3][2]=ffma2(q1.x,w3,a[3][2]); a[3][3]=ffma2(q1.y,w3,a[3][3]);
        }
        __syncthreads();                           // all done reading buf before reuse
    }

    int v = v0 + cl * 4;
    #pragma unroll
    for (int c = 0; c < 4; c++) {                  // col v+c, batches bq*8..+7
        float2 p0 = unpack2(a[c][0]), p1 = unpack2(a[c][1]);
        float2 p2 = unpack2(a[c][2]), p3 = unpack2(a[c][3]);
        float4* o = (float4*)(g_zl[kq] + (size_t)(v+c)*BB + bq*8);
        o[0] = make_float4(p0.x, p0.y, p1.x, p1.y);
        o[1] = make_float4(p2.x, p2.y, p3.x, p3.y);
    }
}

// ---------- sum partials + exp -> g_P, per-block psum ----------
// grid 500, block 128: tid = vl(0..63) + 64*bh(0..1); thread = v, 16 batches.
__global__ __launch_bounds__(128) void k_exps(const float* __restrict__ bs)
{
    __shared__ float sm[64*33 + 128];      // stash rows + red scratch
    int tid = threadIdx.x;
    int vl = tid & 63, bh = tid >> 6;
    int v = blockIdx.x * 64 + vl;
    int boff = bh * 16;

    float w[16];
    #pragma unroll
    for (int j = 0; j < 16; j++) w[j] = 0.f;
    #pragma unroll
    for (int q = 0; q < 4; q++) {
        const float4* p = (const float4*)(g_zl[q] + (size_t)v*BB + boff);
        #pragma unroll
        for (int i = 0; i < 4; i++) {
            float4 x = p[i];
            w[4*i] += x.x; w[4*i+1] += x.y; w[4*i+2] += x.z; w[4*i+3] += x.w;
        }
    }
    float bv = bs[v];
    #pragma unroll
    for (int j = 0; j < 16; j++) w[j] = expf(w[j] + bv);  // |logit| small: safe

    float4* pout = (float4*)(g_P + (size_t)v*BB + boff);
    #pragma unroll
    for (int i = 0; i < 4; i++)
        pout[i] = make_float4(w[4*i], w[4*i+1], w[4*i+2], w[4*i+3]);

    float* srow = sm + vl*33 + boff;
    #pragma unroll
    for (int j = 0; j < 16; j++) srow[j] = w[j];
    __syncthreads();

    {   // two-stage per-batch sum over 64 vocab (deterministic)
        int b2 = tid & 31, sl = tid >> 5;   // 4 slices
        float s = 0.f;
        #pragma unroll 4
        for (int u = sl; u < 64; u += 4) s += sm[u*33 + b2];
        sm[64*33 + sl*32 + b2] = s;
    }
    __syncthreads();
    if (tid < 32) {
        float s = 0.f;
        #pragma unroll
        for (int i = 0; i < 4; i++) s += sm[64*33 + i*32 + tid];
        g_psum[blockIdx.x*BB + tid] = s;
    }
}

// ---------- partial (exp @ E): grid (250 vchunks, 4 dq), cp.async-pipelined ----------
// tid = cl(0..31) + 32*bq(0..3). Thread: d..d+3 (d = dq*128 + cl*4), batches bq*8..+7.
__global__ __launch_bounds__(128, 8) void k_emb(const float* __restrict__ E)
{
    __shared__ __align__(16) float smP[128*BB];    // 16KB: P[128][32]
    __shared__ __align__(16) float Et[2][8*128];   // 2x4KB: E stage [vv][d-chunk]
    int tid = threadIdx.x;
    int cl = tid & 31, bq = tid >> 5;
    int v0 = blockIdx.x * 128;
    int d0 = blockIdx.y * 128;

    const float* esrc = E + (size_t)v0*DD + d0;

    {   // issue stage 0 async load (8 vocab rows x 128 d = 4KB)
        #pragma unroll
        for (int j = 0; j < 2; j++) {
            int c2 = tid + 128*j;
            int kk = c2 >> 5, seg = c2 & 31;
            cp16(sptr(&Et[0][kk*128 + seg*4]), esrc + (size_t)kk*DD + seg*4);
        }
        cp_commit();
    }

    {   // stage P tile with normal loads meanwhile
        const float4* src = (const float4*)g_P + (size_t)v0*8;
        float4* dst = (float4*)smP;
        #pragma unroll
        for (int i = 0; i < 8; i++) dst[tid + 128*i] = src[tid + 128*i];
    }

    unsigned long long a[4][4];                    // [d-col][batch-pair]
    #pragma unroll
    for (int c = 0; c < 4; c++)
        #pragma unroll
        for (int i = 0; i < 4; i++) a[c][i] = 0ULL;

    for (int s = 0; s < 16; s++) {
        if (s + 1 < 16) {
            float* dst = Et[(s+1) & 1];
            #pragma unroll
            for (int j = 0; j < 2; j++) {
                int c2 = tid + 128*j;
                int kk = c2 >> 5, seg = c2 & 31;
                cp16(sptr(dst + kk*128 + seg*4),
                     esrc + (size_t)((s+1)*8 + kk)*DD + seg*4);
            }
        }
        cp_commit();
        cp_wait1();
        __syncthreads();

        const float* ebuf = Et[s & 1];
        #pragma unroll
        for (int kk = 0; kk < 8; kk++) {
            float4 ef = *(const float4*)(ebuf + kk*128 + cl*4);
            unsigned long long e0 = pack2(ef.x, ef.x);
            unsigned long long e1 = pack2(ef.y, ef.y);
            unsigned long long e2 = pack2(ef.z, ef.z);
            unsigned long long e3 = pack2(ef.w, ef.w);
            const ulonglong2* wr = (const ulonglong2*)(smP + (s*8 + kk)*BB + bq*8);
            ulonglong2 q0 = wr[0], q1 = wr[1];
            a[0][0]=ffma2(q0.x,e0,a[0][0]); a[0][1]=ffma2(q0.y,e0,a[0][1]);
            a[0][2]=ffma2(q1.x,e0,a[0][2]); a[0][3]=ffma2(q1.y,e0,a[0][3]);
            a[1][0]=ffma2(q0.x,e1,a[1][0]); a[1][1]=ffma2(q0.y,e1,a[1][1]);
            a[1][2]=ffma2(q1.x,e1,a[1][2]); a[1][3]=ffma2(q1.y,e1,a[1][3]);
            a[2][0]=ffma2(q0.x,e2,a[2][0]); a[2][1]=ffma2(q0.y,e2,a[2][1]);
            a[2][2]=ffma2(q1.x,e2,a[2][2]); a[2][3]=ffma2(q1.y,e2,a[2][3]);
            a[3][0]=ffma2(q0.x,e3,a[3][0]); a[3][1]=ffma2(q0.y,e3,a[3][1]);
            a[3][2]=ffma2(q1.x,e3,a[3][2]); a[3][3]=ffma2(q1.y,e3,a[3][3]);
        }
        __syncthreads();
    }

    int d = d0 + cl * 4;
    int pc = blockIdx.x;                   // 0..249 partial chunk
    float* ob = g_acc + ((size_t)pc*BB)*DD + d;
    #pragma unroll
    for (int i = 0; i < 4; i++) {          // rows bq*8+2i, bq*8+2i+1
        float2 t0 = unpack2(a[0][i]), t1 = unpack2(a[1][i]);
        float2 t2 = unpack2(a[2][i]), t3 = unpack2(a[3][i]);
        *(float4*)(ob + (size_t)(bq*8 + 2*i    )*DD) = make_float4(t0.x, t1.x, t2.x, t3.x);
        *(float4*)(ob + (size_t)(bq*8 + 2*i + 1)*DD) = make_float4(t0.y, t1.y, t2.y, t3.y);
    }
}

// ---------- final reduce: normalize soft embedding, write output ----------
// grid (32 b, 8 dgroups), block 256 (8 slices x 32 float2 lanes)
__global__ __launch_bounds__(256) void k_reduce(float* __restrict__ out, int t) {
    __shared__ float2 red[8][32];
    __shared__ float s_inv;
    int b = blockIdx.x, dg = blockIdx.y;
    int tid = threadIdx.x;
    int s = tid >> 5, d2l = tid & 31;

    float2 a = make_float2(0.f, 0.f);
    const float2* gin = (const float2*)g_acc;
    for (int c = s; c < NVB; c += 8) {
        float2 p = gin[((size_t)c*BB + b)*(DD/2) + dg*32 + d2l];
        a.x += p.x; a.y += p.y;
    }
    red[s][d2l] = a;

    if (tid < 32) {                        // deterministic softmax denominator
        float ts = 0.f;
        for (int c = tid; c < NPB; c += 32) ts += g_psum[c*BB + b];
        #pragma unroll
        for (int o = 16; o > 0; o >>= 1) ts += __shfl_xor_sync(0xffffffffu, ts, o);
        if (tid == 0) s_inv = 1.0f / ts;
    }
    __syncthreads();

    if (s == 0) {
        #pragma unroll
        for (int i = 1; i < 8; i++) { a.x += red[i][d2l].x; a.y += red[i][d2l].y; }
        float inv = s_inv;
        a.x *= inv; a.y *= inv;
        int d2 = dg*32 + d2l;
        ((float2*)g_emb)[b*(DD/2) + d2] = a;
        ((float2*)out)[((size_t)b*TT + t)*(DD/2) + d2] = a;
    }
}

extern "C" void kernel_launch(void* const* d_in, const int* in_sizes, int n_in,
                              void* d_out, int out_size) {
    const float* content = (const float*)d_in[0];
    const float* style   = (const float*)d_in[1];
    const float* E       = (const float*)d_in[2];
    const float* Wk      = (const float*)d_in[3];
    const float* Wr      = (const float*)d_in[4];
    const float* bias    = (const float*)d_in[5];
    const float* Ws      = (const float*)d_in[6];
    const float* bs      = (const float*)d_in[7];
    float* out = (float*)d_out;

    k_init<<<BB, DD>>>(E, out);
    for (int t = 1; t < TT; t++) {
        int cur = t & 1;
        k_lstm_mm<<<dim3(32, NCH), 128>>>(content, style, Wk, Wr, cur);
        k_lstm_fin<<<BB, DD>>>(bias, cur);
        k_zl<<<dim3(250, 4), 128>>>(Ws);
        k_exps<<<NPB, 128>>>(bs);
        k_emb<<<dim3(250, 4), 128>>>(E);
        k_reduce<<<dim3(BB, 8), 256>>>(out, t);
    }
}

// round 12
// speedup vs baseline: 2.9260x; 1.0165x over previous
#include <cuda_runtime.h>
#include <math.h>

// Problem constants (fixed by reference)
#define BB     32          // batch
#define TT     64          // timesteps
#define DD     512         // d_emb / LSTM units
#define H4     2048        // 4 * units
#define VV     32000       // vocab
#define NCH    19          // LSTM K chunks (8 emb + 2 content + 1 style + 8 h)
#define NVB    250         // g_acc partial chunks (128 vocab each)
#define NPB    500         // psum partial blocks (64 vocab each)

// Persistent device state / scratch (no allocations allowed)
__device__ __align__(16) float g_hbuf[2][BB*DD];
__device__ __align__(16) float g_cbuf[2][BB*DD];
__device__ __align__(16) float g_hT[DD*BB];          // h in [k][b] layout
__device__ __align__(16) float g_emb[BB*DD];         // current soft embedding
__device__ __align__(16) float g_zpart[NCH][BB][H4]; // LSTM gate partials
__device__ __align__(16) float g_zl[4][VV*BB];       // logit K-quarter partials
__device__ __align__(16) float g_P[VV*BB];           // exp(logits), [v][b]
__device__ __align__(16) float g_acc[(size_t)NVB*BB*DD]; // weighted-E partials
__device__ __align__(16) float g_psum[NPB*BB];       // exp partial sums

// ---------- packed f32x2 helpers ----------
static __device__ __forceinline__ unsigned long long ffma2(unsigned long long a,
                                                           unsigned long long b,
                                                           unsigned long long c) {
    unsigned long long d;
    asm("fma.rn.f32x2 %0, %1, %2, %3;" : "=l"(d) : "l"(a), "l"(b), "l"(c));
    return d;
}
static __device__ __forceinline__ unsigned long long pack2(float x, float y) {
    unsigned long long r;
    asm("mov.b64 %0, {%1, %2};" : "=l"(r) : "f"(x), "f"(y));
    return r;
}
static __device__ __forceinline__ float2 unpack2(unsigned long long v) {
    float2 r;
    asm("mov.b64 {%0, %1}, %2;" : "=f"(r.x), "=f"(r.y) : "l"(v));
    return r;
}
static __device__ __forceinline__ float sigf(float x) { return 1.0f / (1.0f + expf(-x)); }

// ---------- cp.async (LDGSTS) helpers ----------
static __device__ __forceinline__ unsigned sptr(const void* p) {
    return (unsigned)__cvta_generic_to_shared(p);
}
static __device__ __forceinline__ void cp16(unsigned dst, const void* src) {
    asm volatile("cp.async.cg.shared.global [%0], [%1], 16;\n" :: "r"(dst), "l"(src));
}
static __device__ __forceinline__ void cp_commit() {
    asm volatile("cp.async.commit_group;\n" ::: "memory");
}
static __device__ __forceinline__ void cp_wait1() {
    asm volatile("cp.async.wait_group 1;\n" ::: "memory");
}

// ---------- t = 0: SOS embedding, zero state ----------
__global__ void k_init(const float* __restrict__ E, float* __restrict__ out) {
    int b = blockIdx.x, d = threadIdx.x;       // grid 32, block 512
    float e = E[d];                            // E[SOS=0][d]
    g_emb[b*DD + d] = e;
    out[(size_t)(b*TT)*DD + d] = e;
    g_hbuf[0][b*DD + d] = 0.f;
    g_cbuf[0][b*DD + d] = 0.f;
}

// ---------- LSTM gate GEMM, K-split partials (chunks of 64) ----------
static __device__ __forceinline__ void fma4p(unsigned long long (&acc)[4][2],
                                             float x, const float* wb) {
    unsigned long long x2 = pack2(x, x);
    #pragma unroll
    for (int g = 0; g < 4; g++) {
        float4 w = *(const float4*)(wb + g*DD);
        acc[g][0] = ffma2(pack2(w.x, w.y), x2, acc[g][0]);
        acc[g][1] = ffma2(pack2(w.z, w.w), x2, acc[g][1]);
    }
}

// grid (32, 19), block 128: b = tid>>2, jl = tid&3, 16 j per gate per block
__global__ __launch_bounds__(128) void k_lstm_mm(
    const float* __restrict__ content, const float* __restrict__ style,
    const float* __restrict__ Wk, const float* __restrict__ Wr, int cur)
{
    int tid = threadIdx.x;
    int b  = tid >> 2;                 // 0..31
    int jl = tid & 3;                  // 0..3
    int j0 = blockIdx.x * 16 + jl * 4; // 4 consecutive output units per gate
    int ch = blockIdx.y;               // K chunk 0..18

    unsigned long long acc[4][2];
    #pragma unroll
    for (int g = 0; g < 4; g++) { acc[g][0] = 0ULL; acc[g][1] = 0ULL; }

    const float* Wb; const float* xp; int n;
    if (ch < 8)       { Wb = Wk + (size_t)(ch*64)*H4 + j0;           xp = g_emb + b*DD + ch*64;              n = 64; }
    else if (ch < 10) { Wb = Wk + (size_t)(512+(ch-8)*64)*H4 + j0;   xp = content + b*128 + (ch-8)*64;       n = 64; }
    else if (ch == 10){ Wb = Wk + (size_t)640*H4 + j0;               xp = style + b*16;                      n = 16; }
    else              { Wb = Wr + (size_t)((ch-11)*64)*H4 + j0;      xp = g_hbuf[cur^1] + b*DD + (ch-11)*64; n = 64; }

    #pragma unroll 4
    for (int k = 0; k < n; k++) fma4p(acc, xp[k], Wb + (size_t)k*H4);

    float* zp = &g_zpart[ch][b][0];
    #pragma unroll
    for (int g = 0; g < 4; g++) {
        float2 a = unpack2(acc[g][0]);
        float2 c = unpack2(acc[g][1]);
        *(float4*)(zp + g*DD + j0) = make_float4(a.x, a.y, c.x, c.y);
    }
}

// ---------- LSTM epilogue: reduce chunks, gates, state update ----------
__global__ __launch_bounds__(512) void k_lstm_fin(const float* __restrict__ bias, int cur) {
    int b = blockIdx.x, j = threadIdx.x;   // grid 32, block 512
    float z0 = bias[j], z1 = bias[DD + j], z2 = bias[2*DD + j], z3 = bias[3*DD + j];
    #pragma unroll
    for (int ch = 0; ch < NCH; ch++) {
        const float* zp = &g_zpart[ch][b][0];
        z0 += zp[j]; z1 += zp[DD + j]; z2 += zp[2*DD + j]; z3 += zp[3*DD + j];
    }
    float iv = sigf(z0), fv = sigf(z1), gv = tanhf(z2), ov = sigf(z3);
    float c = fv * g_cbuf[cur ^ 1][b*DD + j] + iv * gv;
    float h = ov * tanhf(c);
    g_cbuf[cur][b*DD + j] = c;
    g_hbuf[cur][b*DD + j] = h;
    g_hT[j*BB + b] = h;                    // k-major for the logits kernel
}

// ---------- partial logits: one K-quarter per block, cp.async 3-stage pipeline ----------
// grid (250, 4 kq), block 128: tid = cl(0..31) + 32*bq(0..3).
// Thread: cols v..v+3 (v = bx*128 + cl*4), batches bq*8..bq*8+7, K=128 in 16 stages of 8.
// 3 stage buffers + ONE barrier per stage: writer of stage s+1 reuses the buffer
// last read at stage s-2, already fenced by the previous iteration's barrier.
__global__ __launch_bounds__(128, 8) void k_zl(const float* __restrict__ Ws)
{
    __shared__ __align__(16) float Hs[128*BB];     // 16KB: one K-quarter of h, [k][b]
    __shared__ __align__(16) float Wt[3][8*128];   // 3x4KB: Ws stage [kk][v-chunk]
    int tid = threadIdx.x;
    int cl = tid & 31, bq = tid >> 5;
    int kq = blockIdx.y;
    int v0 = blockIdx.x * 128;

    const float* wsrc = Ws + (size_t)(kq*128)*VV + v0;
    int kk0 = tid >> 5;                            // this thread's stage row pair
    int seg = tid & 31;

    // issue stage 0 async load (8 k-rows x 128 vocab = 4KB; 2x16B per thread)
    {
        cp16(sptr(&Wt[0][kk0*128 + seg*4]),       wsrc + (size_t)kk0*VV + seg*4);
        cp16(sptr(&Wt[0][(kk0+4)*128 + seg*4]),   wsrc + (size_t)(kk0+4)*VV + seg*4);
        cp_commit();
    }

    {   // stage H quarter (rows kq*128 .. +127) with normal loads meanwhile
        const float4* src = (const float4*)g_hT + kq*1024;
        float4* dst = (float4*)Hs;
        #pragma unroll
        for (int i = 0; i < 8; i++) dst[tid + 128*i] = src[tid + 128*i];
    }

    unsigned long long a[4][4];                    // [col][batch-pair]
    #pragma unroll
    for (int c = 0; c < 4; c++)
        #pragma unroll
        for (int i = 0; i < 4; i++) a[c][i] = 0ULL;

    int r_idx = 0, w_idx = 1;                      // rotating buffer indices
    for (int s = 0; s < 16; s++) {
        if (s + 1 < 16) {                          // prefetch stage s+1
            float* dst = Wt[w_idx];
            cp16(sptr(dst + kk0*128 + seg*4),
                 wsrc + (size_t)((s+1)*8 + kk0)*VV + seg*4);
            cp16(sptr(dst + (kk0+4)*128 + seg*4),
                 wsrc + (size_t)((s+1)*8 + kk0+4)*VV + seg*4);
        }
        cp_commit();
        cp_wait1();                                // stage s landed (this thread)
        __syncthreads();                           // all threads' stage-s data visible

        const float* wbuf = Wt[r_idx];
        #pragma unroll
        for (int kk = 0; kk < 8; kk++) {
            float4 wf = *(const float4*)(wbuf + kk*128 + cl*4);
            unsigned long long w0 = pack2(wf.x, wf.x);
            unsigned long long w1 = pack2(wf.y, wf.y);
            unsigned long long w2 = pack2(wf.z, wf.z);
            unsigned long long w3 = pack2(wf.w, wf.w);
            const ulonglong2* hr = (const ulonglong2*)(Hs + (s*8 + kk)*BB + bq*8);
            ulonglong2 q0 = hr[0], q1 = hr[1];     // 3 broadcast LDS feed 16 FFMA2
            a[0][0]=ffma2(q0.x,w0,a[0][0]); a[0][1]=ffma2(q0.y,w0,a[0][1]);
            a[0][2]=ffma2(q1.x,w0,a[0][2]); a[0][3]=ffma2(q1.y,w0,a[0][3]);
            a[1][0]=ffma2(q0.x,w1,a[1][0]); a[1][1]=ffma2(q0.y,w1,a[1][1]);
            a[1][2]=ffma2(q1.x,w1,a[1][2]); a[1][3]=ffma2(q1.y,w1,a[1][3]);
            a[2][0]=ffma2(q0.x,w2,a[2][0]); a[2][1]=ffma2(q0.y,w2,a[2][1]);
            a[2][2]=ffma2(q1.x,w2,a[2][2]); a[2][3]=ffma2(q1.y,w2,a[2][3]);
            a[3][0]=ffma2(q0.x,w3,a[3][0]); a[3][1]=ffma2(q0.y,w3,a[3][1]);
            a[3][2]=ffma2(q1.x,w3,a[3][2]); a[3][3]=ffma2(q1.y,w3,a[3][3]);
        }
        r_idx = (r_idx == 2) ? 0 : r_idx + 1;
        w_idx = (w_idx == 2) ? 0 : w_idx + 1;
    }

    int v = v0 + cl * 4;
    #pragma unroll
    for (int c = 0; c < 4; c++) {                  // col v+c, batches bq*8..+7
        float2 p0 = unpack2(a[c][0]), p1 = unpack2(a[c][1]);
        float2 p2 = unpack2(a[c][2]), p3 = unpack2(a[c][3]);
        float4* o = (float4*)(g_zl[kq] + (size_t)(v+c)*BB + bq*8);
        o[0] = make_float4(p0.x, p0.y, p1.x, p1.y);
        o[1] = make_float4(p2.x, p2.y, p3.x, p3.y);
    }
}

// ---------- sum partials + exp -> g_P, per-block psum ----------
// grid 500, block 128: tid = vl(0..63) + 64*bh(0..1); thread = v, 16 batches.
__global__ __launch_bounds__(128) void k_exps(const float* __restrict__ bs)
{
    __shared__ float sm[64*33 + 128];      // stash rows + red scratch
    int tid = threadIdx.x;
    int vl = tid & 63, bh = tid >> 6;
    int v = blockIdx.x * 64 + vl;
    int boff = bh * 16;

    float w[16];
    #pragma unroll
    for (int j = 0; j < 16; j++) w[j] = 0.f;
    #pragma unroll
    for (int q = 0; q < 4; q++) {
        const float4* p = (const float4*)(g_zl[q] + (size_t)v*BB + boff);
        #pragma unroll
        for (int i = 0; i < 4; i++) {
            float4 x = p[i];
            w[4*i] += x.x; w[4*i+1] += x.y; w[4*i+2] += x.z; w[4*i+3] += x.w;
        }
    }
    float bv = bs[v];
    #pragma unroll
    for (int j = 0; j < 16; j++) w[j] = expf(w[j] + bv);  // |logit| small: safe

    float4* pout = (float4*)(g_P + (size_t)v*BB + boff);
    #pragma unroll
    for (int i = 0; i < 4; i++)
        pout[i] = make_float4(w[4*i], w[4*i+1], w[4*i+2], w[4*i+3]);

    float* srow = sm + vl*33 + boff;
    #pragma unroll
    for (int j = 0; j < 16; j++) srow[j] = w[j];
    __syncthreads();

    {   // two-stage per-batch sum over 64 vocab (deterministic)
        int b2 = tid & 31, sl = tid >> 5;   // 4 slices
        float s = 0.f;
        #pragma unroll 4
        for (int u = sl; u < 64; u += 4) s += sm[u*33 + b2];
        sm[64*33 + sl*32 + b2] = s;
    }
    __syncthreads();
    if (tid < 32) {
        float s = 0.f;
        #pragma unroll
        for (int i = 0; i < 4; i++) s += sm[64*33 + i*32 + tid];
        g_psum[blockIdx.x*BB + tid] = s;
    }
}

// ---------- partial (exp @ E): grid (250 vchunks, 4 dq), cp.async 3-stage pipeline ----------
// tid = cl(0..31) + 32*bq(0..3). Thread: d..d+3 (d = dq*128 + cl*4), batches bq*8..+7.
__global__ __launch_bounds__(128, 8) void k_emb(const float* __restrict__ E)
{
    __shared__ __align__(16) float smP[128*BB];    // 16KB: P[128][32]
    __shared__ __align__(16) float Et[3][8*128];   // 3x4KB: E stage [vv][d-chunk]
    int tid = threadIdx.x;
    int cl = tid & 31, bq = tid >> 5;
    int v0 = blockIdx.x * 128;
    int d0 = blockIdx.y * 128;

    const float* esrc = E + (size_t)v0*DD + d0;
    int kk0 = tid >> 5;
    int seg = tid & 31;

    {   // issue stage 0 async load (8 vocab rows x 128 d = 4KB)
        cp16(sptr(&Et[0][kk0*128 + seg*4]),     esrc + (size_t)kk0*DD + seg*4);
        cp16(sptr(&Et[0][(kk0+4)*128 + seg*4]), esrc + (size_t)(kk0+4)*DD + seg*4);
        cp_commit();
    }

    {   // stage P tile with normal loads meanwhile
        const float4* src = (const float4*)g_P + (size_t)v0*8;
        float4* dst = (float4*)smP;
        #pragma unroll
        for (int i = 0; i < 8; i++) dst[tid + 128*i] = src[tid + 128*i];
    }

    unsigned long long a[4][4];                    // [d-col][batch-pair]
    #pragma unroll
    for (int c = 0; c < 4; c++)
        #pragma unroll
        for (int i = 0; i < 4; i++) a[c][i] = 0ULL;

    int r_idx = 0, w_idx = 1;
    for (int s = 0; s < 16; s++) {
        if (s + 1 < 16) {
            float* dst = Et[w_idx];
            cp16(sptr(dst + kk0*128 + seg*4),
                 esrc + (size_t)((s+1)*8 + kk0)*DD + seg*4);
            cp16(sptr(dst + (kk0+4)*128 + seg*4),
                 esrc + (size_t)((s+1)*8 + kk0+4)*DD + seg*4);
        }
        cp_commit();
        cp_wait1();
        __syncthreads();

        const float* ebuf = Et[r_idx];
        #pragma unroll
        for (int kk = 0; kk < 8; kk++) {
            float4 ef = *(const float4*)(ebuf + kk*128 + cl*4);
            unsigned long long e0 = pack2(ef.x, ef.x);
            unsigned long long e1 = pack2(ef.y, ef.y);
            unsigned long long e2 = pack2(ef.z, ef.z);
            unsigned long long e3 = pack2(ef.w, ef.w);
            const ulonglong2* wr = (const ulonglong2*)(smP + (s*8 + kk)*BB + bq*8);
            ulonglong2 q0 = wr[0], q1 = wr[1];
            a[0][0]=ffma2(q0.x,e0,a[0][0]); a[0][1]=ffma2(q0.y,e0,a[0][1]);
            a[0][2]=ffma2(q1.x,e0,a[0][2]); a[0][3]=ffma2(q1.y,e0,a[0][3]);
            a[1][0]=ffma2(q0.x,e1,a[1][0]); a[1][1]=ffma2(q0.y,e1,a[1][1]);
            a[1][2]=ffma2(q1.x,e1,a[1][2]); a[1][3]=ffma2(q1.y,e1,a[1][3]);
            a[2][0]=ffma2(q0.x,e2,a[2][0]); a[2][1]=ffma2(q0.y,e2,a[2][1]);
            a[2][2]=ffma2(q1.x,e2,a[2][2]); a[2][3]=ffma2(q1.y,e2,a[2][3]);
            a[3][0]=ffma2(q0.x,e3,a[3][0]); a[3][1]=ffma2(q0.y,e3,a[3][1]);
            a[3][2]=ffma2(q1.x,e3,a[3][2]); a[3][3]=ffma2(q1.y,e3,a[3][3]);
        }
        r_idx = (r_idx == 2) ? 0 : r_idx + 1;
        w_idx = (w_idx == 2) ? 0 : w_idx + 1;
    }

    int d = d0 + cl * 4;
    int pc = blockIdx.x;                   // 0..249 partial chunk
    float* ob = g_acc + ((size_t)pc*BB)*DD + d;
    #pragma unroll
    for (int i = 0; i < 4; i++) {          // rows bq*8+2i, bq*8+2i+1
        float2 t0 = unpack2(a[0][i]), t1 = unpack2(a[1][i]);
        float2 t2 = unpack2(a[2][i]), t3 = unpack2(a[3][i]);
        *(float4*)(ob + (size_t)(bq*8 + 2*i    )*DD) = make_float4(t0.x, t1.x, t2.x, t3.x);
        *(float4*)(ob + (size_t)(bq*8 + 2*i + 1)*DD) = make_float4(t0.y, t1.y, t2.y, t3.y);
    }
}

// ---------- final reduce: normalize soft embedding, write output ----------
// grid (32 b, 8 dgroups), block 256 (8 slices x 32 float2 lanes)
__global__ __launch_bounds__(256) void k_reduce(float* __restrict__ out, int t) {
    __shared__ float2 red[8][32];
    __shared__ float s_inv;
    int b = blockIdx.x, dg = blockIdx.y;
    int tid = threadIdx.x;
    int s = tid >> 5, d2l = tid & 31;

    float2 a = make_float2(0.f, 0.f);
    const float2* gin = (const float2*)g_acc;
    for (int c = s; c < NVB; c += 8) {
        float2 p = gin[((size_t)c*BB + b)*(DD/2) + dg*32 + d2l];
        a.x += p.x; a.y += p.y;
    }
    red[s][d2l] = a;

    if (tid < 32) {                        // deterministic softmax denominator
        float ts = 0.f;
        for (int c = tid; c < NPB; c += 32) ts += g_psum[c*BB + b];
        #pragma unroll
        for (int o = 16; o > 0; o >>= 1) ts += __shfl_xor_sync(0xffffffffu, ts, o);
        if (tid == 0) s_inv = 1.0f / ts;
    }
    __syncthreads();

    if (s == 0) {
        #pragma unroll
        for (int i = 1; i < 8; i++) { a.x += red[i][d2l].x; a.y += red[i][d2l].y; }
        float inv = s_inv;
        a.x *= inv; a.y *= inv;
        int d2 = dg*32 + d2l;
        ((float2*)g_emb)[b*(DD/2) + d2] = a;
        ((float2*)out)[((size_t)b*TT + t)*(DD/2) + d2] = a;
    }
}

extern "C" void kernel_launch(void* const* d_in, const int* in_sizes, int n_in,
                              void* d_out, int out_size) {
    const float* content = (const float*)d_in[0];
    const float* style   = (const float*)d_in[1];
    const float* E       = (const float*)d_in[2];
    const float* Wk      = (const float*)d_in[3];
    const float* Wr      = (const float*)d_in[4];
    const float* bias    = (const float*)d_in[5];
    const float* Ws      = (const float*)d_in[6];
    const float* bs      = (const float*)d_in[7];
    float* out = (float*)d_out;

    k_init<<<BB, DD>>>(E, out);
    for (int t = 1; t < TT; t++) {
        int cur = t & 1;
        k_lstm_mm<<<dim3(32, NCH), 128>>>(content, style, Wk, Wr, cur);
        k_lstm_fin<<<BB, DD>>>(bias, cur);
        k_zl<<<dim3(250, 4), 128>>>(Ws);
        k_exps<<<NPB, 128>>>(bs);
        k_emb<<<dim3(250, 4), 128>>>(E);
        k_reduce<<<dim3(BB, 8), 256>>>(out, t);
    }
}